// round 5
// baseline (speedup 1.0000x reference)
#include <cuda_runtime.h>
#include <math.h>
#include <stdint.h>

#define BATCH 2
#define SEQ   2048
#define DIM   1024
#define HEADS 16
#define DH    64
#define INNER 1024

// ---------------- scratch (device globals; no allocs) ----------------
__device__ float g_h  [BATCH*SEQ*DIM];            // LN output (tf32-rounded)
__device__ float g_qkv[BATCH*3*INNER*SEQ];        // (B, 3*INNER, SEQ)
__device__ float g_q  [BATCH*INNER*SEQ];          // tf32-rounded, scaled
__device__ float g_k  [BATCH*INNER*SEQ];          // tf32-rounded
__device__ float g_v  [BATCH*INNER*SEQ];          // tf32-rounded
__device__ float g_ao [BATCH*SEQ*INNER];          // attention out (tf32-rounded)
__device__ float g_wqkv[3*INNER*DIM];             // tf32-rounded weights
__device__ float g_wout[DIM*INNER];

// ---------------- helpers ----------------
__device__ __forceinline__ float to_tf32(float x) {
    float r;
    asm("cvt.rna.tf32.f32 %0, %1;" : "=f"(r) : "f"(x));
    return r;
}
__device__ __forceinline__ void mma_tf32(float* d, const uint32_t* a, const uint32_t* b) {
    asm volatile(
        "mma.sync.aligned.m16n8k8.row.col.f32.tf32.tf32.f32 "
        "{%0,%1,%2,%3},{%4,%5,%6,%7},{%8,%9},{%0,%1,%2,%3};"
        : "+f"(d[0]), "+f"(d[1]), "+f"(d[2]), "+f"(d[3])
        : "r"(a[0]), "r"(a[1]), "r"(a[2]), "r"(a[3]), "r"(b[0]), "r"(b[1]));
}
__device__ __forceinline__ void cp_async16(void* smem, const void* g) {
    uint32_t s = (uint32_t)__cvta_generic_to_shared(smem);
    asm volatile("cp.async.cg.shared.global [%0], [%1], 16;" :: "r"(s), "l"(g));
}
__device__ __forceinline__ void cp_commit() { asm volatile("cp.async.commit_group;"); }
template <int N>
__device__ __forceinline__ void cp_wait() { asm volatile("cp.async.wait_group %0;" :: "n"(N)); }

// ---------------- tf32 pre-round (weights) ----------------
__global__ __launch_bounds__(256) void cvt_tf32_kernel(const float* __restrict__ src,
                                                       float* __restrict__ dst, int n4) {
    int i = blockIdx.x * 256 + threadIdx.x;
    if (i >= n4) return;
    float4 v = reinterpret_cast<const float4*>(src)[i];
    v.x = to_tf32(v.x); v.y = to_tf32(v.y); v.z = to_tf32(v.z); v.w = to_tf32(v.w);
    reinterpret_cast<float4*>(dst)[i] = v;
}

// ---------------- LayerNorm (writes tf32-rounded) ----------------
__global__ __launch_bounds__(256) void ln_kernel(const float* __restrict__ x,
                                                 const float* __restrict__ gamma,
                                                 const float* __restrict__ beta) {
    int row = blockIdx.x;
    int tid = threadIdx.x;
    const float4* xr = reinterpret_cast<const float4*>(x) + (size_t)row * (DIM/4);
    float4 t = xr[tid];
    float s  = t.x + t.y + t.z + t.w;
    float ss = t.x*t.x + t.y*t.y + t.z*t.z + t.w*t.w;
    #pragma unroll
    for (int o = 16; o > 0; o >>= 1) {
        s  += __shfl_xor_sync(0xffffffffu, s,  o);
        ss += __shfl_xor_sync(0xffffffffu, ss, o);
    }
    __shared__ float ws[8], wss[8];
    int w = tid >> 5, l = tid & 31;
    if (l == 0) { ws[w] = s; wss[w] = ss; }
    __syncthreads();
    if (w == 0) {
        float a = (l < 8) ? ws[l]  : 0.f;
        float b = (l < 8) ? wss[l] : 0.f;
        #pragma unroll
        for (int o = 4; o > 0; o >>= 1) {
            a += __shfl_xor_sync(0xffffffffu, a, o);
            b += __shfl_xor_sync(0xffffffffu, b, o);
        }
        if (l == 0) { ws[0] = a; wss[0] = b; }
    }
    __syncthreads();
    float mu  = ws[0]  * (1.f / DIM);
    float var = wss[0] * (1.f / DIM) - mu * mu;
    float r   = rsqrtf(var + 1e-5f);
    float4 gm = reinterpret_cast<const float4*>(gamma)[tid];
    float4 bt = reinterpret_cast<const float4*>(beta)[tid];
    float4 o;
    o.x = to_tf32((t.x - mu) * r * gm.x + bt.x);
    o.y = to_tf32((t.y - mu) * r * gm.y + bt.y);
    o.z = to_tf32((t.z - mu) * r * gm.z + bt.z);
    o.w = to_tf32((t.w - mu) * r * gm.w + bt.w);
    reinterpret_cast<float4*>(g_h)[(size_t)row * (DIM/4) + tid] = o;
}

// ---------------- TF32 GEMM-NT, cp.async double-buffered ----------------
// C[m][n] = sum_k A[m][k]*B[n][k]. BM=BN=128, BK=16, 256 threads. Inputs pre-rounded.
__global__ __launch_bounds__(256) void gemm_nt_tf32(const float* __restrict__ A,
                                                    const float* __restrict__ B,
                                                    float* __restrict__ C,
                                                    int M, int N, int K,
                                                    long strideB, long strideC) {
    __shared__ __align__(16) float As[2][128 * 20];
    __shared__ __align__(16) float Bs[2][128 * 20];
    const float* Bz = B + (size_t)blockIdx.z * strideB;
    float*       Cz = C + (size_t)blockIdx.z * strideC;
    int m0 = blockIdx.y * 128, n0 = blockIdx.x * 128;
    int tid = threadIdx.x, lane = tid & 31, wid = tid >> 5;
    int wm = (wid & 1) * 64, wn = (wid >> 1) * 32;
    int g = lane >> 2, t = lane & 3;
    float acc[4][4][4] = {};

    int r_ld = tid >> 1;                        // 0..127
    int c_ld = (tid & 1) * 8;                   // 0 or 8: two 16B chunks each
    auto prefetch = [&](int k0, int st) {
        cp_async16(&As[st][r_ld * 20 + c_ld],     A  + (size_t)(m0 + r_ld) * K + k0 + c_ld);
        cp_async16(&As[st][r_ld * 20 + c_ld + 4], A  + (size_t)(m0 + r_ld) * K + k0 + c_ld + 4);
        cp_async16(&Bs[st][r_ld * 20 + c_ld],     Bz + (size_t)(n0 + r_ld) * K + k0 + c_ld);
        cp_async16(&Bs[st][r_ld * 20 + c_ld + 4], Bz + (size_t)(n0 + r_ld) * K + k0 + c_ld + 4);
    };

    prefetch(0, 0); cp_commit();
    int nT = K / 16;
    for (int it = 0; it < nT; it++) {
        int st = it & 1;
        if (it + 1 < nT) { prefetch((it + 1) * 16, st ^ 1); cp_commit(); cp_wait<1>(); }
        else             { cp_wait<0>(); }
        __syncthreads();
        #pragma unroll
        for (int ks = 0; ks < 16; ks += 8) {
            uint32_t aR[4][4], bR[4][2];
            #pragma unroll
            for (int mf = 0; mf < 4; mf++) {
                int mb = wm + mf * 16;
                aR[mf][0] = *reinterpret_cast<uint32_t*>(&As[st][(mb + g    ) * 20 + ks + t    ]);
                aR[mf][1] = *reinterpret_cast<uint32_t*>(&As[st][(mb + g + 8) * 20 + ks + t    ]);
                aR[mf][2] = *reinterpret_cast<uint32_t*>(&As[st][(mb + g    ) * 20 + ks + t + 4]);
                aR[mf][3] = *reinterpret_cast<uint32_t*>(&As[st][(mb + g + 8) * 20 + ks + t + 4]);
            }
            #pragma unroll
            for (int nf = 0; nf < 4; nf++) {
                int nb = wn + nf * 8;
                bR[nf][0] = *reinterpret_cast<uint32_t*>(&Bs[st][(nb + g) * 20 + ks + t    ]);
                bR[nf][1] = *reinterpret_cast<uint32_t*>(&Bs[st][(nb + g) * 20 + ks + t + 4]);
            }
            #pragma unroll
            for (int mf = 0; mf < 4; mf++)
                #pragma unroll
                for (int nf = 0; nf < 4; nf++)
                    mma_tf32(acc[mf][nf], aR[mf], bR[nf]);
        }
        __syncthreads();
    }

    #pragma unroll
    for (int mf = 0; mf < 4; mf++)
        #pragma unroll
        for (int nf = 0; nf < 4; nf++) {
            int m = m0 + wm + mf * 16 + g;
            int n = n0 + wn + nf * 8 + 2 * t;
            *reinterpret_cast<float2*>(Cz + (size_t)m * N + n) =
                make_float2(acc[mf][nf][0], acc[mf][nf][1]);
            *reinterpret_cast<float2*>(Cz + (size_t)(m + 8) * N + n) =
                make_float2(acc[mf][nf][2], acc[mf][nf][3]);
        }
}

// ---------------- depthwise causal conv (writes tf32-rounded) ----------------
__global__ __launch_bounds__(256) void conv_kernel(
    const float* __restrict__ const* wptr) {
    int p = blockIdx.y;
    int idx = blockIdx.x * 256 + threadIdx.x;
    int n = idx & (SEQ - 1);
    int c = (idx >> 11) & (INNER - 1);
    int b = idx >> 21;
    const float* row = g_qkv + ((size_t)b * 3 * INNER + (size_t)p * INNER + c) * SEQ;
    int g = c >> 8, cg = c & 255;
    float acc;
    if (g == 0) {
        acc = row[n];
    } else {
        int ksz = 2 * g + 1;
        const float* w  = wptr[p * 6 + (g - 1) * 2] + cg * ksz;
        const float* bb = wptr[p * 6 + (g - 1) * 2 + 1];
        acc = bb[cg];
        for (int t = 0; t < ksz; t++) {
            int m = n - (ksz - 1) + t;
            if (m >= 0) acc += w[t] * row[m];
        }
    }
    float scale = (p == 0) ? 0.125f : 1.0f;
    float* dst = (p == 0 ? g_q : (p == 1 ? g_k : g_v));
    dst[((size_t)b * INNER + c) * SEQ + n] = to_tf32(acc * scale);
}

__device__ const float* g_convw[18];
__global__ void set_convw(const float* a0, const float* a1, const float* a2, const float* a3,
                          const float* a4, const float* a5, const float* a6, const float* a7,
                          const float* a8, const float* a9, const float* a10, const float* a11,
                          const float* a12, const float* a13, const float* a14, const float* a15,
                          const float* a16, const float* a17) {
    g_convw[0]=a0; g_convw[1]=a1; g_convw[2]=a2; g_convw[3]=a3; g_convw[4]=a4; g_convw[5]=a5;
    g_convw[6]=a6; g_convw[7]=a7; g_convw[8]=a8; g_convw[9]=a9; g_convw[10]=a10; g_convw[11]=a11;
    g_convw[12]=a12; g_convw[13]=a13; g_convw[14]=a14; g_convw[15]=a15; g_convw[16]=a16; g_convw[17]=a17;
}

// ---------------- tensor-core flash attention (TF32, cp.async 2-stage K/V) ----------------
#define SSTR 72
#define TILE_F (64 * SSTR)
__global__ __launch_bounds__(128) void attn_tc(const float* __restrict__ slopes) {
    extern __shared__ float sm[];
    // layout: K0, V0, K1, V1, QP
    float* QPs = sm + 4 * TILE_F;

    int it = blockIdx.x, i0 = it * 64;
    int bh = blockIdx.y, b = bh >> 4, h = bh & 15;
    float slope = slopes[h];
    int tid = threadIdx.x, lane = tid & 31, w = tid >> 5;
    int g = lane >> 2, t = lane & 3;
    int mb = w * 16;
    const float* Qb = g_q + (size_t)bh * DH * SEQ;
    const float* Kb = g_k + (size_t)bh * DH * SEQ;
    const float* Vb = g_v + (size_t)bh * DH * SEQ;

    int d_ld  = tid >> 1;                       // row 0..63
    int c_ld  = (tid & 1) * 32;                 // column half: [0,32) or [32,64)
    auto prefetch = [&](int j0, int st) {
        float* Ks = sm + (2 * st) * TILE_F;
        float* Vs = sm + (2 * st + 1) * TILE_F;
        const float* kp = Kb + (size_t)d_ld * SEQ + j0 + c_ld;
        const float* vp = Vb + (size_t)d_ld * SEQ + j0 + c_ld;
        float* ks = &Ks[d_ld * SSTR + c_ld];
        float* vs = &Vs[d_ld * SSTR + c_ld];
        #pragma unroll
        for (int q = 0; q < 8; q++) {           // 8 x 16B = full 32-col half-row
            cp_async16(ks + q * 4, kp + q * 4);
            cp_async16(vs + q * 4, vp + q * 4);
        }
    };

    prefetch(0, 0); cp_commit();

    // fill Q tile [d][i] (already tf32-rounded in gmem)
    #pragma unroll
    for (int ii = 0; ii < 8; ii++) {
        int f = tid + 128 * ii, d = f >> 4, c4 = f & 15;
        float4 v = *reinterpret_cast<const float4*>(Qb + (size_t)d * SEQ + i0 + c4 * 4);
        *reinterpret_cast<float4*>(&QPs[d * SSTR + c4 * 4]) = v;
    }
    __syncthreads();

    uint32_t aQ[8][4];
    #pragma unroll
    for (int ks = 0; ks < 8; ks++) {
        aQ[ks][0] = *reinterpret_cast<uint32_t*>(&QPs[(ks*8 + t    ) * SSTR + mb + g    ]);
        aQ[ks][1] = *reinterpret_cast<uint32_t*>(&QPs[(ks*8 + t    ) * SSTR + mb + g + 8]);
        aQ[ks][2] = *reinterpret_cast<uint32_t*>(&QPs[(ks*8 + t + 4) * SSTR + mb + g    ]);
        aQ[ks][3] = *reinterpret_cast<uint32_t*>(&QPs[(ks*8 + t + 4) * SSTR + mb + g + 8]);
    }
    __syncthreads();   // QPs reused for P below

    float o[8][4] = {};
    float m0 = -1e30f, m1 = -1e30f, l0 = 0.f, l1 = 0.f;

    for (int jt = 0; jt <= it; jt++) {
        int st = jt & 1;
        if (jt < it) { prefetch((jt + 1) * 64, st ^ 1); cp_commit(); cp_wait<1>(); }
        else         { cp_wait<0>(); }
        __syncthreads();
        float* Ks = sm + (2 * st) * TILE_F;
        float* Vs = sm + (2 * st + 1) * TILE_F;
        int j0 = jt * 64;

        // S = Q K^T
        float sF[8][4] = {};
        #pragma unroll
        for (int ks = 0; ks < 8; ks++) {
            #pragma unroll
            for (int nf = 0; nf < 8; nf++) {
                uint32_t bR[2];
                bR[0] = *reinterpret_cast<uint32_t*>(&Ks[(ks*8 + t    ) * SSTR + nf*8 + g]);
                bR[1] = *reinterpret_cast<uint32_t*>(&Ks[(ks*8 + t + 4) * SSTR + nf*8 + g]);
                mma_tf32(sF[nf], aQ[ks], bR);
            }
        }

        // bias + mask + online softmax
        int ir0 = i0 + mb + g, ir1 = ir0 + 8;
        float mloc0 = -1e30f, mloc1 = -1e30f;
        #pragma unroll
        for (int nf = 0; nf < 8; nf++) {
            int jc = j0 + nf*8 + 2*t;
            float v0 = sF[nf][0] + slope * (float)(jc     - ir0);
            float v1 = sF[nf][1] + slope * (float)(jc + 1 - ir0);
            float v2 = sF[nf][2] + slope * (float)(jc     - ir1);
            float v3 = sF[nf][3] + slope * (float)(jc + 1 - ir1);
            if (jc     > ir0) v0 = -1e30f;
            if (jc + 1 > ir0) v1 = -1e30f;
            if (jc     > ir1) v2 = -1e30f;
            if (jc + 1 > ir1) v3 = -1e30f;
            sF[nf][0] = v0; sF[nf][1] = v1; sF[nf][2] = v2; sF[nf][3] = v3;
            mloc0 = fmaxf(mloc0, fmaxf(v0, v1));
            mloc1 = fmaxf(mloc1, fmaxf(v2, v3));
        }
        mloc0 = fmaxf(mloc0, __shfl_xor_sync(0xffffffffu, mloc0, 1));
        mloc0 = fmaxf(mloc0, __shfl_xor_sync(0xffffffffu, mloc0, 2));
        mloc1 = fmaxf(mloc1, __shfl_xor_sync(0xffffffffu, mloc1, 1));
        mloc1 = fmaxf(mloc1, __shfl_xor_sync(0xffffffffu, mloc1, 2));
        float mn0 = fmaxf(m0, mloc0), mn1 = fmaxf(m1, mloc1);
        float sc0 = __expf(m0 - mn0), sc1 = __expf(m1 - mn1);
        float sum0 = 0.f, sum1 = 0.f;
        #pragma unroll
        for (int nf = 0; nf < 8; nf++) {
            sF[nf][0] = __expf(sF[nf][0] - mn0); sum0 += sF[nf][0];
            sF[nf][1] = __expf(sF[nf][1] - mn0); sum0 += sF[nf][1];
            sF[nf][2] = __expf(sF[nf][2] - mn1); sum1 += sF[nf][2];
            sF[nf][3] = __expf(sF[nf][3] - mn1); sum1 += sF[nf][3];
        }
        sum0 += __shfl_xor_sync(0xffffffffu, sum0, 1);
        sum0 += __shfl_xor_sync(0xffffffffu, sum0, 2);
        sum1 += __shfl_xor_sync(0xffffffffu, sum1, 1);
        sum1 += __shfl_xor_sync(0xffffffffu, sum1, 2);
        l0 = l0 * sc0 + sum0; l1 = l1 * sc1 + sum1;
        m0 = mn0; m1 = mn1;
        #pragma unroll
        for (int nf = 0; nf < 8; nf++) {
            o[nf][0] *= sc0; o[nf][1] *= sc0;
            o[nf][2] *= sc1; o[nf][3] *= sc1;
        }

        // store P (tf32) into warp-private QPs rows
        #pragma unroll
        for (int nf = 0; nf < 8; nf++) {
            *reinterpret_cast<float2*>(&QPs[(mb + g    ) * SSTR + nf*8 + 2*t]) =
                make_float2(to_tf32(sF[nf][0]), to_tf32(sF[nf][1]));
            *reinterpret_cast<float2*>(&QPs[(mb + g + 8) * SSTR + nf*8 + 2*t]) =
                make_float2(to_tf32(sF[nf][2]), to_tf32(sF[nf][3]));
        }
        __syncwarp();

        // O += P V
        #pragma unroll
        for (int ks = 0; ks < 8; ks++) {
            uint32_t aP[4];
            aP[0] = *reinterpret_cast<uint32_t*>(&QPs[(mb + g    ) * SSTR + ks*8 + t    ]);
            aP[1] = *reinterpret_cast<uint32_t*>(&QPs[(mb + g + 8) * SSTR + ks*8 + t    ]);
            aP[2] = *reinterpret_cast<uint32_t*>(&QPs[(mb + g    ) * SSTR + ks*8 + t + 4]);
            aP[3] = *reinterpret_cast<uint32_t*>(&QPs[(mb + g + 8) * SSTR + ks*8 + t + 4]);
            #pragma unroll
            for (int nf = 0; nf < 8; nf++) {
                uint32_t bR[2];
                bR[0] = *reinterpret_cast<uint32_t*>(&Vs[(nf*8 + g) * SSTR + ks*8 + t    ]);
                bR[1] = *reinterpret_cast<uint32_t*>(&Vs[(nf*8 + g) * SSTR + ks*8 + t + 4]);
                mma_tf32(o[nf], aP, bR);
            }
        }
        __syncthreads();   // all warps done with Ks/Vs[st] before it is prefetched again
    }

    float inv0 = 1.f / l0, inv1 = 1.f / l1;
    int r0 = i0 + mb + g;
    #pragma unroll
    for (int nf = 0; nf < 8; nf++) {
        int col = h * DH + nf*8 + 2*t;
        *reinterpret_cast<float2*>(&g_ao[((size_t)b * SEQ + r0    ) * INNER + col]) =
            make_float2(to_tf32(o[nf][0] * inv0), to_tf32(o[nf][1] * inv0));
        *reinterpret_cast<float2*>(&g_ao[((size_t)b * SEQ + r0 + 8) * INNER + col]) =
            make_float2(to_tf32(o[nf][2] * inv1), to_tf32(o[nf][3] * inv1));
    }
}

// ---------------- launch ----------------
extern "C" void kernel_launch(void* const* d_in, const int* in_sizes, int n_in,
                              void* d_out, int out_size) {
    const float* x      = (const float*)d_in[0];
    const float* gamma  = (const float*)d_in[1];
    const float* beta   = (const float*)d_in[2];
    const float* w_qkv  = (const float*)d_in[3];
    const float* slopes = (const float*)d_in[22];
    const float* w_out  = (const float*)d_in[23];

    float *ph, *pqkv, *pao, *pwqkv, *pwout;
    cudaGetSymbolAddress((void**)&ph,    g_h);
    cudaGetSymbolAddress((void**)&pqkv,  g_qkv);
    cudaGetSymbolAddress((void**)&pao,   g_ao);
    cudaGetSymbolAddress((void**)&pwqkv, g_wqkv);
    cudaGetSymbolAddress((void**)&pwout, g_wout);
    const float** pconvw;
    cudaGetSymbolAddress((void**)&pconvw, g_convw);

    // 0) stash conv weight pointers + pre-round weights to tf32
    set_convw<<<1, 1>>>(
        (const float*)d_in[4],  (const float*)d_in[5],  (const float*)d_in[6],
        (const float*)d_in[7],  (const float*)d_in[8],  (const float*)d_in[9],
        (const float*)d_in[10], (const float*)d_in[11], (const float*)d_in[12],
        (const float*)d_in[13], (const float*)d_in[14], (const float*)d_in[15],
        (const float*)d_in[16], (const float*)d_in[17], (const float*)d_in[18],
        (const float*)d_in[19], (const float*)d_in[20], (const float*)d_in[21]);
    cvt_tf32_kernel<<<(3*INNER*DIM/4 + 255)/256, 256>>>(w_qkv, pwqkv, 3*INNER*DIM/4);
    cvt_tf32_kernel<<<(DIM*INNER/4   + 255)/256, 256>>>(w_out, pwout, DIM*INNER/4);

    // 1) LayerNorm (tf32-rounded out)
    ln_kernel<<<BATCH * SEQ, 256>>>(x, gamma, beta);

    // 2) QKV GEMM
    gemm_nt_tf32<<<dim3(SEQ/128, 3*INNER/128, BATCH), 256>>>(
        pwqkv, ph, pqkv, 3*INNER, SEQ, DIM,
        (long)SEQ * DIM, (long)3 * INNER * SEQ);

    // 3) depthwise causal convs (tf32-rounded out, q scaled)
    int convBlocks = (BATCH * INNER * SEQ) / 256;
    conv_kernel<<<dim3(convBlocks, 3), 256>>>((const float* const*)pconvw);

    // 4) tensor-core flash attention (2-stage cp.async K/V)
    size_t smem = (size_t)(5 * TILE_F) * sizeof(float);  // 92160 B
    cudaFuncSetAttribute(attn_tc, cudaFuncAttributeMaxDynamicSharedMemorySize, (int)smem);
    attn_tc<<<dim3(SEQ/64, BATCH*HEADS), 128, smem>>>(slopes);

    // 5) output projection
    gemm_nt_tf32<<<dim3(DIM/128, (BATCH*SEQ)/128, 1), 256>>>(
        pao, pwout, (float*)d_out, BATCH*SEQ, DIM, INNER, 0, 0);
}

// round 6
// speedup vs baseline: 1.0156x; 1.0156x over previous
#include <cuda_runtime.h>
#include <math.h>
#include <stdint.h>

#define BATCH 2
#define SEQ   2048
#define DIM   1024
#define HEADS 16
#define DH    64
#define INNER 1024

// ---------------- scratch (device globals; no allocs) ----------------
__device__ float g_h  [BATCH*SEQ*DIM];            // LN output (tf32-rounded)
__device__ float g_qkv[BATCH*3*INNER*SEQ];        // (B, 3*INNER, SEQ)
__device__ float g_q  [BATCH*INNER*SEQ];          // tf32-rounded, scaled
__device__ float g_k  [BATCH*INNER*SEQ];          // tf32-rounded
__device__ float g_v  [BATCH*INNER*SEQ];          // tf32-rounded
__device__ float g_ao [BATCH*SEQ*INNER];          // attention out (tf32-rounded)
__device__ float g_wqkv[3*INNER*DIM];             // tf32-rounded weights
__device__ float g_wout[DIM*INNER];

// ---------------- helpers ----------------
__device__ __forceinline__ float to_tf32(float x) {
    float r;
    asm("cvt.rna.tf32.f32 %0, %1;" : "=f"(r) : "f"(x));
    return r;
}
__device__ __forceinline__ void mma_tf32(float* d, const uint32_t* a, const uint32_t* b) {
    asm volatile(
        "mma.sync.aligned.m16n8k8.row.col.f32.tf32.tf32.f32 "
        "{%0,%1,%2,%3},{%4,%5,%6,%7},{%8,%9},{%0,%1,%2,%3};"
        : "+f"(d[0]), "+f"(d[1]), "+f"(d[2]), "+f"(d[3])
        : "r"(a[0]), "r"(a[1]), "r"(a[2]), "r"(a[3]), "r"(b[0]), "r"(b[1]));
}
__device__ __forceinline__ void cp_async16(void* smem, const void* g) {
    uint32_t s = (uint32_t)__cvta_generic_to_shared(smem);
    asm volatile("cp.async.cg.shared.global [%0], [%1], 16;" :: "r"(s), "l"(g));
}
__device__ __forceinline__ void cp_commit() { asm volatile("cp.async.commit_group;"); }
template <int N>
__device__ __forceinline__ void cp_wait() { asm volatile("cp.async.wait_group %0;" :: "n"(N)); }

// ---------------- tf32 pre-round (weights) ----------------
__global__ __launch_bounds__(256) void cvt_tf32_kernel(const float* __restrict__ src,
                                                       float* __restrict__ dst, int n4) {
    int i = blockIdx.x * 256 + threadIdx.x;
    if (i >= n4) return;
    float4 v = reinterpret_cast<const float4*>(src)[i];
    v.x = to_tf32(v.x); v.y = to_tf32(v.y); v.z = to_tf32(v.z); v.w = to_tf32(v.w);
    reinterpret_cast<float4*>(dst)[i] = v;
}

// ---------------- LayerNorm (writes tf32-rounded) ----------------
__global__ __launch_bounds__(256) void ln_kernel(const float* __restrict__ x,
                                                 const float* __restrict__ gamma,
                                                 const float* __restrict__ beta) {
    int row = blockIdx.x;
    int tid = threadIdx.x;
    const float4* xr = reinterpret_cast<const float4*>(x) + (size_t)row * (DIM/4);
    float4 t = xr[tid];
    float s  = t.x + t.y + t.z + t.w;
    float ss = t.x*t.x + t.y*t.y + t.z*t.z + t.w*t.w;
    #pragma unroll
    for (int o = 16; o > 0; o >>= 1) {
        s  += __shfl_xor_sync(0xffffffffu, s,  o);
        ss += __shfl_xor_sync(0xffffffffu, ss, o);
    }
    __shared__ float ws[8], wss[8];
    int w = tid >> 5, l = tid & 31;
    if (l == 0) { ws[w] = s; wss[w] = ss; }
    __syncthreads();
    if (w == 0) {
        float a = (l < 8) ? ws[l]  : 0.f;
        float b = (l < 8) ? wss[l] : 0.f;
        #pragma unroll
        for (int o = 4; o > 0; o >>= 1) {
            a += __shfl_xor_sync(0xffffffffu, a, o);
            b += __shfl_xor_sync(0xffffffffu, b, o);
        }
        if (l == 0) { ws[0] = a; wss[0] = b; }
    }
    __syncthreads();
    float mu  = ws[0]  * (1.f / DIM);
    float var = wss[0] * (1.f / DIM) - mu * mu;
    float r   = rsqrtf(var + 1e-5f);
    float4 gm = reinterpret_cast<const float4*>(gamma)[tid];
    float4 bt = reinterpret_cast<const float4*>(beta)[tid];
    float4 o;
    o.x = to_tf32((t.x - mu) * r * gm.x + bt.x);
    o.y = to_tf32((t.y - mu) * r * gm.y + bt.y);
    o.z = to_tf32((t.z - mu) * r * gm.z + bt.z);
    o.w = to_tf32((t.w - mu) * r * gm.w + bt.w);
    reinterpret_cast<float4*>(g_h)[(size_t)row * (DIM/4) + tid] = o;
}

// ---------------- TF32 GEMM-NT, cp.async double-buffered ----------------
__global__ __launch_bounds__(256) void gemm_nt_tf32(const float* __restrict__ A,
                                                    const float* __restrict__ B,
                                                    float* __restrict__ C,
                                                    int M, int N, int K,
                                                    long strideB, long strideC) {
    __shared__ __align__(16) float As[2][128 * 20];
    __shared__ __align__(16) float Bs[2][128 * 20];
    const float* Bz = B + (size_t)blockIdx.z * strideB;
    float*       Cz = C + (size_t)blockIdx.z * strideC;
    int m0 = blockIdx.y * 128, n0 = blockIdx.x * 128;
    int tid = threadIdx.x, lane = tid & 31, wid = tid >> 5;
    int wm = (wid & 1) * 64, wn = (wid >> 1) * 32;
    int g = lane >> 2, t = lane & 3;
    float acc[4][4][4] = {};

    int r_ld = tid >> 1;
    int c_ld = (tid & 1) * 8;
    auto prefetch = [&](int k0, int st) {
        cp_async16(&As[st][r_ld * 20 + c_ld],     A  + (size_t)(m0 + r_ld) * K + k0 + c_ld);
        cp_async16(&As[st][r_ld * 20 + c_ld + 4], A  + (size_t)(m0 + r_ld) * K + k0 + c_ld + 4);
        cp_async16(&Bs[st][r_ld * 20 + c_ld],     Bz + (size_t)(n0 + r_ld) * K + k0 + c_ld);
        cp_async16(&Bs[st][r_ld * 20 + c_ld + 4], Bz + (size_t)(n0 + r_ld) * K + k0 + c_ld + 4);
    };

    prefetch(0, 0); cp_commit();
    int nT = K / 16;
    for (int it = 0; it < nT; it++) {
        int st = it & 1;
        if (it + 1 < nT) { prefetch((it + 1) * 16, st ^ 1); cp_commit(); cp_wait<1>(); }
        else             { cp_wait<0>(); }
        __syncthreads();
        #pragma unroll
        for (int ks = 0; ks < 16; ks += 8) {
            uint32_t aR[4][4], bR[4][2];
            #pragma unroll
            for (int mf = 0; mf < 4; mf++) {
                int mb = wm + mf * 16;
                aR[mf][0] = *reinterpret_cast<uint32_t*>(&As[st][(mb + g    ) * 20 + ks + t    ]);
                aR[mf][1] = *reinterpret_cast<uint32_t*>(&As[st][(mb + g + 8) * 20 + ks + t    ]);
                aR[mf][2] = *reinterpret_cast<uint32_t*>(&As[st][(mb + g    ) * 20 + ks + t + 4]);
                aR[mf][3] = *reinterpret_cast<uint32_t*>(&As[st][(mb + g + 8) * 20 + ks + t + 4]);
            }
            #pragma unroll
            for (int nf = 0; nf < 4; nf++) {
                int nb = wn + nf * 8;
                bR[nf][0] = *reinterpret_cast<uint32_t*>(&Bs[st][(nb + g) * 20 + ks + t    ]);
                bR[nf][1] = *reinterpret_cast<uint32_t*>(&Bs[st][(nb + g) * 20 + ks + t + 4]);
            }
            #pragma unroll
            for (int mf = 0; mf < 4; mf++)
                #pragma unroll
                for (int nf = 0; nf < 4; nf++)
                    mma_tf32(acc[mf][nf], aR[mf], bR[nf]);
        }
        __syncthreads();
    }

    #pragma unroll
    for (int mf = 0; mf < 4; mf++)
        #pragma unroll
        for (int nf = 0; nf < 4; nf++) {
            int m = m0 + wm + mf * 16 + g;
            int n = n0 + wn + nf * 8 + 2 * t;
            *reinterpret_cast<float2*>(Cz + (size_t)m * N + n) =
                make_float2(acc[mf][nf][0], acc[mf][nf][1]);
            *reinterpret_cast<float2*>(Cz + (size_t)(m + 8) * N + n) =
                make_float2(acc[mf][nf][2], acc[mf][nf][3]);
        }
}

// ---------------- depthwise causal conv (writes tf32-rounded) ----------------
__global__ __launch_bounds__(256) void conv_kernel(
    const float* __restrict__ const* wptr) {
    int p = blockIdx.y;
    int idx = blockIdx.x * 256 + threadIdx.x;
    int n = idx & (SEQ - 1);
    int c = (idx >> 11) & (INNER - 1);
    int b = idx >> 21;
    const float* row = g_qkv + ((size_t)b * 3 * INNER + (size_t)p * INNER + c) * SEQ;
    int g = c >> 8, cg = c & 255;
    float acc;
    if (g == 0) {
        acc = row[n];
    } else {
        int ksz = 2 * g + 1;
        const float* w  = wptr[p * 6 + (g - 1) * 2] + cg * ksz;
        const float* bb = wptr[p * 6 + (g - 1) * 2 + 1];
        acc = bb[cg];
        for (int t = 0; t < ksz; t++) {
            int m = n - (ksz - 1) + t;
            if (m >= 0) acc += w[t] * row[m];
        }
    }
    float scale = (p == 0) ? 0.125f : 1.0f;
    float* dst = (p == 0 ? g_q : (p == 1 ? g_k : g_v));
    dst[((size_t)b * INNER + c) * SEQ + n] = to_tf32(acc * scale);
}

__device__ const float* g_convw[18];
__global__ void set_convw(const float* a0, const float* a1, const float* a2, const float* a3,
                          const float* a4, const float* a5, const float* a6, const float* a7,
                          const float* a8, const float* a9, const float* a10, const float* a11,
                          const float* a12, const float* a13, const float* a14, const float* a15,
                          const float* a16, const float* a17) {
    g_convw[0]=a0; g_convw[1]=a1; g_convw[2]=a2; g_convw[3]=a3; g_convw[4]=a4; g_convw[5]=a5;
    g_convw[6]=a6; g_convw[7]=a7; g_convw[8]=a8; g_convw[9]=a9; g_convw[10]=a10; g_convw[11]=a11;
    g_convw[12]=a12; g_convw[13]=a13; g_convw[14]=a14; g_convw[15]=a15; g_convw[16]=a16; g_convw[17]=a17;
}

// ---------------- tensor-core flash attention (TF32, BM=128, 8 warps) ----------------
// Q/K/V (B,H,Dh,N) channel-major. 128 query rows per CTA, 64-col K/V tiles,
// K/V double-buffered cp.async, P in dedicated smem, Q frags direct from gmem.
#define SSTR 72
#define TILE_F (64 * SSTR)
__global__ __launch_bounds__(256) void attn_tc(const float* __restrict__ slopes) {
    extern __shared__ float sm[];
    // layout: K0, V0, K1, V1, P(128 x SSTR)
    float* Ps = sm + 4 * TILE_F;

    int it = blockIdx.x, i0 = it * 128;
    int bh = blockIdx.y, b = bh >> 4, h = bh & 15;
    float slope = slopes[h];
    int tid = threadIdx.x, lane = tid & 31, w = tid >> 5;
    int g = lane >> 2, t = lane & 3;
    int mb = w * 16;                         // warp rows [mb, mb+16) of 128
    const float* Qb = g_q + (size_t)bh * DH * SEQ;
    const float* Kb = g_k + (size_t)bh * DH * SEQ;
    const float* Vb = g_v + (size_t)bh * DH * SEQ;

    int half = tid >> 7;                     // 0 -> K, 1 -> V
    int r    = tid & 127;
    int d_ld = r >> 1, c_ld = (r & 1) * 32;
    const float* srcb = half ? Vb : Kb;
    auto prefetch = [&](int j0, int st) {
        const float* src = srcb + (size_t)d_ld * SEQ + j0 + c_ld;
        float* dst = sm + (2 * st + half) * TILE_F + d_ld * SSTR + c_ld;
        #pragma unroll
        for (int q = 0; q < 8; q++)          // 8 x 16B = 32-col half-row
            cp_async16(dst + q * 4, src + q * 4);
    };

    prefetch(0, 0); cp_commit();

    // Q frags straight from gmem (tf32-rounded there already)
    int iq = i0 + mb + g;
    uint32_t aQ[8][4];
    #pragma unroll
    for (int ks = 0; ks < 8; ks++) {
        const float* row0 = Qb + (size_t)(ks*8 + t    ) * SEQ;
        const float* row4 = Qb + (size_t)(ks*8 + t + 4) * SEQ;
        aQ[ks][0] = *reinterpret_cast<const uint32_t*>(row0 + iq);
        aQ[ks][1] = *reinterpret_cast<const uint32_t*>(row0 + iq + 8);
        aQ[ks][2] = *reinterpret_cast<const uint32_t*>(row4 + iq);
        aQ[ks][3] = *reinterpret_cast<const uint32_t*>(row4 + iq + 8);
    }

    float o[8][4] = {};
    float m0 = -1e30f, m1 = -1e30f, l0 = 0.f, l1 = 0.f;
    int jt_max = 2 * it + 1;

    for (int jt = 0; jt <= jt_max; jt++) {
        int st = jt & 1;
        if (jt < jt_max) { prefetch((jt + 1) * 64, st ^ 1); cp_commit(); cp_wait<1>(); }
        else             { cp_wait<0>(); }
        __syncthreads();
        float* Ks = sm + (2 * st) * TILE_F;
        float* Vs = sm + (2 * st + 1) * TILE_F;
        int j0 = jt * 64;

        // S = Q K^T
        float sF[8][4] = {};
        #pragma unroll
        for (int ks = 0; ks < 8; ks++) {
            #pragma unroll
            for (int nf = 0; nf < 8; nf++) {
                uint32_t bR[2];
                bR[0] = *reinterpret_cast<uint32_t*>(&Ks[(ks*8 + t    ) * SSTR + nf*8 + g]);
                bR[1] = *reinterpret_cast<uint32_t*>(&Ks[(ks*8 + t + 4) * SSTR + nf*8 + g]);
                mma_tf32(sF[nf], aQ[ks], bR);
            }
        }

        // bias + mask + online softmax
        int ir0 = i0 + mb + g, ir1 = ir0 + 8;
        float mloc0 = -1e30f, mloc1 = -1e30f;
        #pragma unroll
        for (int nf = 0; nf < 8; nf++) {
            int jc = j0 + nf*8 + 2*t;
            float v0 = sF[nf][0] + slope * (float)(jc     - ir0);
            float v1 = sF[nf][1] + slope * (float)(jc + 1 - ir0);
            float v2 = sF[nf][2] + slope * (float)(jc     - ir1);
            float v3 = sF[nf][3] + slope * (float)(jc + 1 - ir1);
            if (jc     > ir0) v0 = -1e30f;
            if (jc + 1 > ir0) v1 = -1e30f;
            if (jc     > ir1) v2 = -1e30f;
            if (jc + 1 > ir1) v3 = -1e30f;
            sF[nf][0] = v0; sF[nf][1] = v1; sF[nf][2] = v2; sF[nf][3] = v3;
            mloc0 = fmaxf(mloc0, fmaxf(v0, v1));
            mloc1 = fmaxf(mloc1, fmaxf(v2, v3));
        }
        mloc0 = fmaxf(mloc0, __shfl_xor_sync(0xffffffffu, mloc0, 1));
        mloc0 = fmaxf(mloc0, __shfl_xor_sync(0xffffffffu, mloc0, 2));
        mloc1 = fmaxf(mloc1, __shfl_xor_sync(0xffffffffu, mloc1, 1));
        mloc1 = fmaxf(mloc1, __shfl_xor_sync(0xffffffffu, mloc1, 2));
        float mn0 = fmaxf(m0, mloc0), mn1 = fmaxf(m1, mloc1);
        float sc0 = __expf(m0 - mn0), sc1 = __expf(m1 - mn1);
        float sum0 = 0.f, sum1 = 0.f;
        #pragma unroll
        for (int nf = 0; nf < 8; nf++) {
            sF[nf][0] = __expf(sF[nf][0] - mn0); sum0 += sF[nf][0];
            sF[nf][1] = __expf(sF[nf][1] - mn0); sum0 += sF[nf][1];
            sF[nf][2] = __expf(sF[nf][2] - mn1); sum1 += sF[nf][2];
            sF[nf][3] = __expf(sF[nf][3] - mn1); sum1 += sF[nf][3];
        }
        sum0 += __shfl_xor_sync(0xffffffffu, sum0, 1);
        sum0 += __shfl_xor_sync(0xffffffffu, sum0, 2);
        sum1 += __shfl_xor_sync(0xffffffffu, sum1, 1);
        sum1 += __shfl_xor_sync(0xffffffffu, sum1, 2);
        l0 = l0 * sc0 + sum0; l1 = l1 * sc1 + sum1;
        m0 = mn0; m1 = mn1;
        #pragma unroll
        for (int nf = 0; nf < 8; nf++) {
            o[nf][0] *= sc0; o[nf][1] *= sc0;
            o[nf][2] *= sc1; o[nf][3] *= sc1;
        }

        // store P (tf32) into warp-private Ps rows [mb, mb+16)
        #pragma unroll
        for (int nf = 0; nf < 8; nf++) {
            *reinterpret_cast<float2*>(&Ps[(mb + g    ) * SSTR + nf*8 + 2*t]) =
                make_float2(to_tf32(sF[nf][0]), to_tf32(sF[nf][1]));
            *reinterpret_cast<float2*>(&Ps[(mb + g + 8) * SSTR + nf*8 + 2*t]) =
                make_float2(to_tf32(sF[nf][2]), to_tf32(sF[nf][3]));
        }
        __syncwarp();

        // O += P V
        #pragma unroll
        for (int ks = 0; ks < 8; ks++) {
            uint32_t aP[4];
            aP[0] = *reinterpret_cast<uint32_t*>(&Ps[(mb + g    ) * SSTR + ks*8 + t    ]);
            aP[1] = *reinterpret_cast<uint32_t*>(&Ps[(mb + g + 8) * SSTR + ks*8 + t    ]);
            aP[2] = *reinterpret_cast<uint32_t*>(&Ps[(mb + g    ) * SSTR + ks*8 + t + 4]);
            aP[3] = *reinterpret_cast<uint32_t*>(&Ps[(mb + g + 8) * SSTR + ks*8 + t + 4]);
            #pragma unroll
            for (int nf = 0; nf < 8; nf++) {
                uint32_t bR[2];
                bR[0] = *reinterpret_cast<uint32_t*>(&Vs[(nf*8 + g) * SSTR + ks*8 + t    ]);
                bR[1] = *reinterpret_cast<uint32_t*>(&Vs[(nf*8 + g) * SSTR + ks*8 + t + 4]);
                mma_tf32(o[nf], aP, bR);
            }
        }
        __syncthreads();   // all warps done with buffer st before its next refill
    }

    float inv0 = 1.f / l0, inv1 = 1.f / l1;
    int r0 = i0 + mb + g;
    #pragma unroll
    for (int nf = 0; nf < 8; nf++) {
        int col = h * DH + nf*8 + 2*t;
        *reinterpret_cast<float2*>(&g_ao[((size_t)b * SEQ + r0    ) * INNER + col]) =
            make_float2(to_tf32(o[nf][0] * inv0), to_tf32(o[nf][1] * inv0));
        *reinterpret_cast<float2*>(&g_ao[((size_t)b * SEQ + r0 + 8) * INNER + col]) =
            make_float2(to_tf32(o[nf][2] * inv1), to_tf32(o[nf][3] * inv1));
    }
}

// ---------------- launch ----------------
extern "C" void kernel_launch(void* const* d_in, const int* in_sizes, int n_in,
                              void* d_out, int out_size) {
    const float* x      = (const float*)d_in[0];
    const float* gamma  = (const float*)d_in[1];
    const float* beta   = (const float*)d_in[2];
    const float* w_qkv  = (const float*)d_in[3];
    const float* slopes = (const float*)d_in[22];
    const float* w_out  = (const float*)d_in[23];

    float *ph, *pqkv, *pao, *pwqkv, *pwout;
    cudaGetSymbolAddress((void**)&ph,    g_h);
    cudaGetSymbolAddress((void**)&pqkv,  g_qkv);
    cudaGetSymbolAddress((void**)&pao,   g_ao);
    cudaGetSymbolAddress((void**)&pwqkv, g_wqkv);
    cudaGetSymbolAddress((void**)&pwout, g_wout);
    const float** pconvw;
    cudaGetSymbolAddress((void**)&pconvw, g_convw);

    // 0) stash conv weight pointers + pre-round weights to tf32
    set_convw<<<1, 1>>>(
        (const float*)d_in[4],  (const float*)d_in[5],  (const float*)d_in[6],
        (const float*)d_in[7],  (const float*)d_in[8],  (const float*)d_in[9],
        (const float*)d_in[10], (const float*)d_in[11], (const float*)d_in[12],
        (const float*)d_in[13], (const float*)d_in[14], (const float*)d_in[15],
        (const float*)d_in[16], (const float*)d_in[17], (const float*)d_in[18],
        (const float*)d_in[19], (const float*)d_in[20], (const float*)d_in[21]);
    cvt_tf32_kernel<<<(3*INNER*DIM/4 + 255)/256, 256>>>(w_qkv, pwqkv, 3*INNER*DIM/4);
    cvt_tf32_kernel<<<(DIM*INNER/4   + 255)/256, 256>>>(w_out, pwout, DIM*INNER/4);

    // 1) LayerNorm (tf32-rounded out)
    ln_kernel<<<BATCH * SEQ, 256>>>(x, gamma, beta);

    // 2) QKV GEMM
    gemm_nt_tf32<<<dim3(SEQ/128, 3*INNER/128, BATCH), 256>>>(
        pwqkv, ph, pqkv, 3*INNER, SEQ, DIM,
        (long)SEQ * DIM, (long)3 * INNER * SEQ);

    // 3) depthwise causal convs (tf32-rounded out, q scaled)
    int convBlocks = (BATCH * INNER * SEQ) / 256;
    conv_kernel<<<dim3(convBlocks, 3), 256>>>((const float* const*)pconvw);

    // 4) tensor-core flash attention, BM=128, 8 warps
    size_t smem = (size_t)(4 * TILE_F + 128 * SSTR) * sizeof(float);  // 110592 B
    cudaFuncSetAttribute(attn_tc, cudaFuncAttributeMaxDynamicSharedMemorySize, (int)smem);
    attn_tc<<<dim3(SEQ/128, BATCH*HEADS), 256, smem>>>(slopes);

    // 5) output projection
    gemm_nt_tf32<<<dim3(DIM/128, (BATCH*SEQ)/128, 1), 256>>>(
        pao, pwout, (float*)d_out, BATCH*SEQ, DIM, INNER, 0, 0);
}

// round 7
// speedup vs baseline: 1.1278x; 1.1105x over previous
#include <cuda_runtime.h>
#include <math.h>
#include <stdint.h>

#define BATCH 2
#define SEQ   2048
#define DIM   1024
#define HEADS 16
#define DH    64
#define INNER 1024

// ---------------- scratch (device globals; no allocs) ----------------
__device__ float g_h  [BATCH*SEQ*DIM];            // LN output (tf32-rounded)
__device__ float g_qkv[BATCH*3*INNER*SEQ];        // (B, 3*INNER, SEQ)
__device__ float g_q  [BATCH*INNER*SEQ];          // tf32-rounded, scaled
__device__ float g_k  [BATCH*INNER*SEQ];          // tf32-rounded
__device__ float g_v  [BATCH*INNER*SEQ];          // tf32-rounded
__device__ float g_ao [BATCH*SEQ*INNER];          // attention out (tf32-rounded)
__device__ float g_wqkv[3*INNER*DIM];             // tf32-rounded weights
__device__ float g_wout[DIM*INNER];

// ---------------- helpers ----------------
__device__ __forceinline__ float to_tf32(float x) {
    float r;
    asm("cvt.rna.tf32.f32 %0, %1;" : "=f"(r) : "f"(x));
    return r;
}
__device__ __forceinline__ void mma_tf32(float* d, const uint32_t* a, const uint32_t* b) {
    asm volatile(
        "mma.sync.aligned.m16n8k8.row.col.f32.tf32.tf32.f32 "
        "{%0,%1,%2,%3},{%4,%5,%6,%7},{%8,%9},{%0,%1,%2,%3};"
        : "+f"(d[0]), "+f"(d[1]), "+f"(d[2]), "+f"(d[3])
        : "r"(a[0]), "r"(a[1]), "r"(a[2]), "r"(a[3]), "r"(b[0]), "r"(b[1]));
}

// ---------------- tf32 pre-round (weights) ----------------
__global__ __launch_bounds__(256) void cvt_tf32_kernel(const float* __restrict__ src,
                                                       float* __restrict__ dst, int n4) {
    int i = blockIdx.x * 256 + threadIdx.x;
    if (i >= n4) return;
    float4 v = reinterpret_cast<const float4*>(src)[i];
    v.x = to_tf32(v.x); v.y = to_tf32(v.y); v.z = to_tf32(v.z); v.w = to_tf32(v.w);
    reinterpret_cast<float4*>(dst)[i] = v;
}

// ---------------- LayerNorm (writes tf32-rounded) ----------------
__global__ __launch_bounds__(256) void ln_kernel(const float* __restrict__ x,
                                                 const float* __restrict__ gamma,
                                                 const float* __restrict__ beta) {
    int row = blockIdx.x;
    int tid = threadIdx.x;
    const float4* xr = reinterpret_cast<const float4*>(x) + (size_t)row * (DIM/4);
    float4 t = xr[tid];
    float s  = t.x + t.y + t.z + t.w;
    float ss = t.x*t.x + t.y*t.y + t.z*t.z + t.w*t.w;
    #pragma unroll
    for (int o = 16; o > 0; o >>= 1) {
        s  += __shfl_xor_sync(0xffffffffu, s,  o);
        ss += __shfl_xor_sync(0xffffffffu, ss, o);
    }
    __shared__ float ws[8], wss[8];
    int w = tid >> 5, l = tid & 31;
    if (l == 0) { ws[w] = s; wss[w] = ss; }
    __syncthreads();
    if (w == 0) {
        float a = (l < 8) ? ws[l]  : 0.f;
        float b = (l < 8) ? wss[l] : 0.f;
        #pragma unroll
        for (int o = 4; o > 0; o >>= 1) {
            a += __shfl_xor_sync(0xffffffffu, a, o);
            b += __shfl_xor_sync(0xffffffffu, b, o);
        }
        if (l == 0) { ws[0] = a; wss[0] = b; }
    }
    __syncthreads();
    float mu  = ws[0]  * (1.f / DIM);
    float var = wss[0] * (1.f / DIM) - mu * mu;
    float r   = rsqrtf(var + 1e-5f);
    float4 gm = reinterpret_cast<const float4*>(gamma)[tid];
    float4 bt = reinterpret_cast<const float4*>(beta)[tid];
    float4 o;
    o.x = to_tf32((t.x - mu) * r * gm.x + bt.x);
    o.y = to_tf32((t.y - mu) * r * gm.y + bt.y);
    o.z = to_tf32((t.z - mu) * r * gm.z + bt.z);
    o.w = to_tf32((t.w - mu) * r * gm.w + bt.w);
    reinterpret_cast<float4*>(g_h)[(size_t)row * (DIM/4) + tid] = o;
}

// ---------------- TF32 GEMM-NT (R3 structure, raw float4 loaders) ----------------
// C[m][n] = sum_k A[m][k]*B[n][k]. BM=BN=128, BK=16, 256 threads. Inputs pre-rounded.
__global__ __launch_bounds__(256) void gemm_nt_tf32(const float* __restrict__ A,
                                                    const float* __restrict__ B,
                                                    float* __restrict__ C,
                                                    int M, int N, int K,
                                                    long strideB, long strideC) {
    __shared__ __align__(16) float As[128 * 20];   // [m][k], pad 20
    __shared__ __align__(16) float Bs[128 * 20];   // [n][k]
    const float* Bz = B + (size_t)blockIdx.z * strideB;
    float*       Cz = C + (size_t)blockIdx.z * strideC;
    int m0 = blockIdx.y * 128, n0 = blockIdx.x * 128;
    int tid = threadIdx.x, lane = tid & 31, wid = tid >> 5;
    int wm = (wid & 1) * 64, wn = (wid >> 1) * 32;
    int g = lane >> 2, t = lane & 3;
    float acc[4][4][4] = {};

    for (int k0 = 0; k0 < K; k0 += 16) {
        #pragma unroll
        for (int i = 0; i < 2; i++) {
            int f = tid + 256 * i;          // 0..511
            int r = f >> 2, c4 = f & 3;
            float4 a = *reinterpret_cast<const float4*>(A  + (size_t)(m0 + r) * K + k0 + c4 * 4);
            *reinterpret_cast<float4*>(&As[r * 20 + c4 * 4]) = a;
            float4 b = *reinterpret_cast<const float4*>(Bz + (size_t)(n0 + r) * K + k0 + c4 * 4);
            *reinterpret_cast<float4*>(&Bs[r * 20 + c4 * 4]) = b;
        }
        __syncthreads();
        #pragma unroll
        for (int ks = 0; ks < 16; ks += 8) {
            uint32_t aR[4][4], bR[4][2];
            #pragma unroll
            for (int mf = 0; mf < 4; mf++) {
                int mb = wm + mf * 16;
                aR[mf][0] = *reinterpret_cast<uint32_t*>(&As[(mb + g    ) * 20 + ks + t    ]);
                aR[mf][1] = *reinterpret_cast<uint32_t*>(&As[(mb + g + 8) * 20 + ks + t    ]);
                aR[mf][2] = *reinterpret_cast<uint32_t*>(&As[(mb + g    ) * 20 + ks + t + 4]);
                aR[mf][3] = *reinterpret_cast<uint32_t*>(&As[(mb + g + 8) * 20 + ks + t + 4]);
            }
            #pragma unroll
            for (int nf = 0; nf < 4; nf++) {
                int nb = wn + nf * 8;
                bR[nf][0] = *reinterpret_cast<uint32_t*>(&Bs[(nb + g) * 20 + ks + t    ]);
                bR[nf][1] = *reinterpret_cast<uint32_t*>(&Bs[(nb + g) * 20 + ks + t + 4]);
            }
            #pragma unroll
            for (int mf = 0; mf < 4; mf++)
                #pragma unroll
                for (int nf = 0; nf < 4; nf++)
                    mma_tf32(acc[mf][nf], aR[mf], bR[nf]);
        }
        __syncthreads();
    }

    #pragma unroll
    for (int mf = 0; mf < 4; mf++)
        #pragma unroll
        for (int nf = 0; nf < 4; nf++) {
            int m = m0 + wm + mf * 16 + g;
            int n = n0 + wn + nf * 8 + 2 * t;
            *reinterpret_cast<float2*>(Cz + (size_t)m * N + n) =
                make_float2(acc[mf][nf][0], acc[mf][nf][1]);
            *reinterpret_cast<float2*>(Cz + (size_t)(m + 8) * N + n) =
                make_float2(acc[mf][nf][2], acc[mf][nf][3]);
        }
}

// ---------------- depthwise causal conv (writes tf32-rounded) ----------------
__global__ __launch_bounds__(256) void conv_kernel(
    const float* __restrict__ const* wptr) {
    int p = blockIdx.y;
    int idx = blockIdx.x * 256 + threadIdx.x;
    int n = idx & (SEQ - 1);
    int c = (idx >> 11) & (INNER - 1);
    int b = idx >> 21;
    const float* row = g_qkv + ((size_t)b * 3 * INNER + (size_t)p * INNER + c) * SEQ;
    int g = c >> 8, cg = c & 255;
    float acc;
    if (g == 0) {
        acc = row[n];
    } else {
        int ksz = 2 * g + 1;
        const float* w  = wptr[p * 6 + (g - 1) * 2] + cg * ksz;
        const float* bb = wptr[p * 6 + (g - 1) * 2 + 1];
        acc = bb[cg];
        for (int t = 0; t < ksz; t++) {
            int m = n - (ksz - 1) + t;
            if (m >= 0) acc += w[t] * row[m];
        }
    }
    float scale = (p == 0) ? 0.125f : 1.0f;
    float* dst = (p == 0 ? g_q : (p == 1 ? g_k : g_v));
    dst[((size_t)b * INNER + c) * SEQ + n] = to_tf32(acc * scale);
}

__device__ const float* g_convw[18];
__global__ void set_convw(const float* a0, const float* a1, const float* a2, const float* a3,
                          const float* a4, const float* a5, const float* a6, const float* a7,
                          const float* a8, const float* a9, const float* a10, const float* a11,
                          const float* a12, const float* a13, const float* a14, const float* a15,
                          const float* a16, const float* a17) {
    g_convw[0]=a0; g_convw[1]=a1; g_convw[2]=a2; g_convw[3]=a3; g_convw[4]=a4; g_convw[5]=a5;
    g_convw[6]=a6; g_convw[7]=a7; g_convw[8]=a8; g_convw[9]=a9; g_convw[10]=a10; g_convw[11]=a11;
    g_convw[12]=a12; g_convw[13]=a13; g_convw[14]=a14; g_convw[15]=a15; g_convw[16]=a16; g_convw[17]=a17;
}

// ---------------- tensor-core flash attention (R3 structure, raw loads) ----------------
// Q/K/V in (B,H,Dh,N) channel-major (pre-rounded). 64 rows/block, 64-col tiles, 4 warps.
#define SSTR 72
__global__ __launch_bounds__(128) void attn_tc(const float* __restrict__ slopes) {
    extern __shared__ float sm[];
    float* Ks  = sm;                 // [d][j] 64 x 72
    float* Vs  = Ks + 64*SSTR;       // [d][j]
    float* QPs = Vs + 64*SSTR;       // Q: [d][i], later P: [i][j]

    int it = blockIdx.x, i0 = it * 64;
    int bh = blockIdx.y, b = bh >> 4, h = bh & 15;
    float slope = slopes[h];
    int tid = threadIdx.x, lane = tid & 31, w = tid >> 5;
    int g = lane >> 2, t = lane & 3;
    int mb = w * 16;
    const float* Qb = g_q + (size_t)bh * DH * SEQ;
    const float* Kb = g_k + (size_t)bh * DH * SEQ;
    const float* Vb = g_v + (size_t)bh * DH * SEQ;

    // fill Q tile [d][i] (raw copy — pre-rounded in gmem)
    #pragma unroll
    for (int ii = 0; ii < 8; ii++) {
        int f = tid + 128 * ii, d = f >> 4, c4 = f & 15;
        float4 v = *reinterpret_cast<const float4*>(Qb + (size_t)d * SEQ + i0 + c4 * 4);
        *reinterpret_cast<float4*>(&QPs[d * SSTR + c4 * 4]) = v;
    }
    __syncthreads();

    // Q frags held in registers for the whole j loop
    uint32_t aQ[8][4];
    #pragma unroll
    for (int ks = 0; ks < 8; ks++) {
        aQ[ks][0] = *reinterpret_cast<uint32_t*>(&QPs[(ks*8 + t    ) * SSTR + mb + g    ]);
        aQ[ks][1] = *reinterpret_cast<uint32_t*>(&QPs[(ks*8 + t    ) * SSTR + mb + g + 8]);
        aQ[ks][2] = *reinterpret_cast<uint32_t*>(&QPs[(ks*8 + t + 4) * SSTR + mb + g    ]);
        aQ[ks][3] = *reinterpret_cast<uint32_t*>(&QPs[(ks*8 + t + 4) * SSTR + mb + g + 8]);
    }

    float o[8][4] = {};
    float m0 = -1e30f, m1 = -1e30f, l0 = 0.f, l1 = 0.f;

    for (int jt = 0; jt <= it; jt++) {
        int j0 = jt * 64;
        __syncthreads();                       // QPs(P) WAR + Ks/Vs reuse
        #pragma unroll
        for (int ii = 0; ii < 8; ii++) {       // fill K/V tiles [d][j] (raw copy)
            int f = tid + 128 * ii, d = f >> 4, c4 = f & 15;
            float4 kv = *reinterpret_cast<const float4*>(Kb + (size_t)d * SEQ + j0 + c4 * 4);
            *reinterpret_cast<float4*>(&Ks[d * SSTR + c4 * 4]) = kv;
            float4 vv = *reinterpret_cast<const float4*>(Vb + (size_t)d * SEQ + j0 + c4 * 4);
            *reinterpret_cast<float4*>(&Vs[d * SSTR + c4 * 4]) = vv;
        }
        __syncthreads();

        // S = Q K^T
        float sF[8][4] = {};
        #pragma unroll
        for (int ks = 0; ks < 8; ks++) {
            #pragma unroll
            for (int nf = 0; nf < 8; nf++) {
                uint32_t bR[2];
                bR[0] = *reinterpret_cast<uint32_t*>(&Ks[(ks*8 + t    ) * SSTR + nf*8 + g]);
                bR[1] = *reinterpret_cast<uint32_t*>(&Ks[(ks*8 + t + 4) * SSTR + nf*8 + g]);
                mma_tf32(sF[nf], aQ[ks], bR);
            }
        }

        // bias + causal mask + online softmax
        int ir0 = i0 + mb + g, ir1 = ir0 + 8;
        float mloc0 = -1e30f, mloc1 = -1e30f;
        #pragma unroll
        for (int nf = 0; nf < 8; nf++) {
            int jc = j0 + nf*8 + 2*t;
            float v0 = sF[nf][0] + slope * (float)(jc     - ir0);
            float v1 = sF[nf][1] + slope * (float)(jc + 1 - ir0);
            float v2 = sF[nf][2] + slope * (float)(jc     - ir1);
            float v3 = sF[nf][3] + slope * (float)(jc + 1 - ir1);
            if (jc     > ir0) v0 = -1e30f;
            if (jc + 1 > ir0) v1 = -1e30f;
            if (jc     > ir1) v2 = -1e30f;
            if (jc + 1 > ir1) v3 = -1e30f;
            sF[nf][0] = v0; sF[nf][1] = v1; sF[nf][2] = v2; sF[nf][3] = v3;
            mloc0 = fmaxf(mloc0, fmaxf(v0, v1));
            mloc1 = fmaxf(mloc1, fmaxf(v2, v3));
        }
        mloc0 = fmaxf(mloc0, __shfl_xor_sync(0xffffffffu, mloc0, 1));
        mloc0 = fmaxf(mloc0, __shfl_xor_sync(0xffffffffu, mloc0, 2));
        mloc1 = fmaxf(mloc1, __shfl_xor_sync(0xffffffffu, mloc1, 1));
        mloc1 = fmaxf(mloc1, __shfl_xor_sync(0xffffffffu, mloc1, 2));
        float mn0 = fmaxf(m0, mloc0), mn1 = fmaxf(m1, mloc1);
        float sc0 = __expf(m0 - mn0), sc1 = __expf(m1 - mn1);
        float sum0 = 0.f, sum1 = 0.f;
        #pragma unroll
        for (int nf = 0; nf < 8; nf++) {
            sF[nf][0] = __expf(sF[nf][0] - mn0); sum0 += sF[nf][0];
            sF[nf][1] = __expf(sF[nf][1] - mn0); sum0 += sF[nf][1];
            sF[nf][2] = __expf(sF[nf][2] - mn1); sum1 += sF[nf][2];
            sF[nf][3] = __expf(sF[nf][3] - mn1); sum1 += sF[nf][3];
        }
        sum0 += __shfl_xor_sync(0xffffffffu, sum0, 1);
        sum0 += __shfl_xor_sync(0xffffffffu, sum0, 2);
        sum1 += __shfl_xor_sync(0xffffffffu, sum1, 1);
        sum1 += __shfl_xor_sync(0xffffffffu, sum1, 2);
        l0 = l0 * sc0 + sum0; l1 = l1 * sc1 + sum1;
        m0 = mn0; m1 = mn1;
        #pragma unroll
        for (int nf = 0; nf < 8; nf++) {
            o[nf][0] *= sc0; o[nf][1] *= sc0;
            o[nf][2] *= sc1; o[nf][3] *= sc1;
        }

        // store P (tf32) into warp-private QPs rows
        #pragma unroll
        for (int nf = 0; nf < 8; nf++) {
            *reinterpret_cast<float2*>(&QPs[(mb + g    ) * SSTR + nf*8 + 2*t]) =
                make_float2(to_tf32(sF[nf][0]), to_tf32(sF[nf][1]));
            *reinterpret_cast<float2*>(&QPs[(mb + g + 8) * SSTR + nf*8 + 2*t]) =
                make_float2(to_tf32(sF[nf][2]), to_tf32(sF[nf][3]));
        }
        __syncwarp();

        // O += P V
        #pragma unroll
        for (int ks = 0; ks < 8; ks++) {
            uint32_t aP[4];
            aP[0] = *reinterpret_cast<uint32_t*>(&QPs[(mb + g    ) * SSTR + ks*8 + t    ]);
            aP[1] = *reinterpret_cast<uint32_t*>(&QPs[(mb + g + 8) * SSTR + ks*8 + t    ]);
            aP[2] = *reinterpret_cast<uint32_t*>(&QPs[(mb + g    ) * SSTR + ks*8 + t + 4]);
            aP[3] = *reinterpret_cast<uint32_t*>(&QPs[(mb + g + 8) * SSTR + ks*8 + t + 4]);
            #pragma unroll
            for (int nf = 0; nf < 8; nf++) {
                uint32_t bR[2];
                bR[0] = *reinterpret_cast<uint32_t*>(&Vs[(nf*8 + g) * SSTR + ks*8 + t    ]);
                bR[1] = *reinterpret_cast<uint32_t*>(&Vs[(nf*8 + g) * SSTR + ks*8 + t + 4]);
                mma_tf32(o[nf], aP, bR);
            }
        }
    }

    // normalize + write (B,N,INNER), tf32-rounded for the out-proj
    float inv0 = 1.f / l0, inv1 = 1.f / l1;
    int r0 = i0 + mb + g;
    #pragma unroll
    for (int nf = 0; nf < 8; nf++) {
        int col = h * DH + nf*8 + 2*t;
        *reinterpret_cast<float2*>(&g_ao[((size_t)b * SEQ + r0    ) * INNER + col]) =
            make_float2(to_tf32(o[nf][0] * inv0), to_tf32(o[nf][1] * inv0));
        *reinterpret_cast<float2*>(&g_ao[((size_t)b * SEQ + r0 + 8) * INNER + col]) =
            make_float2(to_tf32(o[nf][2] * inv1), to_tf32(o[nf][3] * inv1));
    }
}

// ---------------- launch ----------------
extern "C" void kernel_launch(void* const* d_in, const int* in_sizes, int n_in,
                              void* d_out, int out_size) {
    const float* x      = (const float*)d_in[0];
    const float* gamma  = (const float*)d_in[1];
    const float* beta   = (const float*)d_in[2];
    const float* w_qkv  = (const float*)d_in[3];
    const float* slopes = (const float*)d_in[22];
    const float* w_out  = (const float*)d_in[23];

    float *ph, *pqkv, *pao, *pwqkv, *pwout;
    cudaGetSymbolAddress((void**)&ph,    g_h);
    cudaGetSymbolAddress((void**)&pqkv,  g_qkv);
    cudaGetSymbolAddress((void**)&pao,   g_ao);
    cudaGetSymbolAddress((void**)&pwqkv, g_wqkv);
    cudaGetSymbolAddress((void**)&pwout, g_wout);
    const float** pconvw;
    cudaGetSymbolAddress((void**)&pconvw, g_convw);

    // 0) stash conv weight pointers + pre-round weights to tf32
    set_convw<<<1, 1>>>(
        (const float*)d_in[4],  (const float*)d_in[5],  (const float*)d_in[6],
        (const float*)d_in[7],  (const float*)d_in[8],  (const float*)d_in[9],
        (const float*)d_in[10], (const float*)d_in[11], (const float*)d_in[12],
        (const float*)d_in[13], (const float*)d_in[14], (const float*)d_in[15],
        (const float*)d_in[16], (const float*)d_in[17], (const float*)d_in[18],
        (const float*)d_in[19], (const float*)d_in[20], (const float*)d_in[21]);
    cvt_tf32_kernel<<<(3*INNER*DIM/4 + 255)/256, 256>>>(w_qkv, pwqkv, 3*INNER*DIM/4);
    cvt_tf32_kernel<<<(DIM*INNER/4   + 255)/256, 256>>>(w_out, pwout, DIM*INNER/4);

    // 1) LayerNorm (tf32-rounded out)
    ln_kernel<<<BATCH * SEQ, 256>>>(x, gamma, beta);

    // 2) QKV GEMM
    gemm_nt_tf32<<<dim3(SEQ/128, 3*INNER/128, BATCH), 256>>>(
        pwqkv, ph, pqkv, 3*INNER, SEQ, DIM,
        (long)SEQ * DIM, (long)3 * INNER * SEQ);

    // 3) depthwise causal convs (tf32-rounded out, q scaled)
    int convBlocks = (BATCH * INNER * SEQ) / 256;
    conv_kernel<<<dim3(convBlocks, 3), 256>>>((const float* const*)pconvw);

    // 4) tensor-core flash attention (R3 structure)
    size_t smem = (size_t)(3 * 64 * SSTR) * sizeof(float);  // 55296 B
    cudaFuncSetAttribute(attn_tc, cudaFuncAttributeMaxDynamicSharedMemorySize, (int)smem);
    attn_tc<<<dim3(SEQ/64, BATCH*HEADS), 128, smem>>>(slopes);

    // 5) output projection
    gemm_nt_tf32<<<dim3(DIM/128, (BATCH*SEQ)/128, 1), 256>>>(
        pao, pwout, (float*)d_out, BATCH*SEQ, DIM, INNER, 0, 0);
}

// round 8
// speedup vs baseline: 1.5206x; 1.3484x over previous
#include <cuda_runtime.h>
#include <cuda_fp16.h>
#include <math.h>
#include <stdint.h>

#define BATCH 2
#define SEQ   2048
#define DIM   1024
#define HEADS 16
#define DH    64
#define INNER 1024

// ---------------- scratch (device globals; no allocs) ----------------
__device__ __half g_h  [BATCH*SEQ*DIM];           // LN output (fp16)
__device__ float  g_qkv[BATCH*3*INNER*SEQ];       // (B, 3*INNER, SEQ) fp32
__device__ float  g_q  [BATCH*INNER*SEQ];         // tf32-rounded, scaled
__device__ float  g_k  [BATCH*INNER*SEQ];         // tf32-rounded
__device__ float  g_v  [BATCH*INNER*SEQ];         // tf32-rounded
__device__ __half g_ao [BATCH*SEQ*INNER];         // attention out (fp16)
__device__ __half g_wqkv[3*INNER*DIM];            // fp16 weights
__device__ __half g_wout[DIM*INNER];

// ---------------- helpers ----------------
__device__ __forceinline__ float to_tf32(float x) {
    float r;
    asm("cvt.rna.tf32.f32 %0, %1;" : "=f"(r) : "f"(x));
    return r;
}
__device__ __forceinline__ void mma_tf32(float* d, const uint32_t* a, const uint32_t* b) {
    asm volatile(
        "mma.sync.aligned.m16n8k8.row.col.f32.tf32.tf32.f32 "
        "{%0,%1,%2,%3},{%4,%5,%6,%7},{%8,%9},{%0,%1,%2,%3};"
        : "+f"(d[0]), "+f"(d[1]), "+f"(d[2]), "+f"(d[3])
        : "r"(a[0]), "r"(a[1]), "r"(a[2]), "r"(a[3]), "r"(b[0]), "r"(b[1]));
}
__device__ __forceinline__ void mma_f16(float* d, const uint32_t* a, const uint32_t* b) {
    asm volatile(
        "mma.sync.aligned.m16n8k16.row.col.f32.f16.f16.f32 "
        "{%0,%1,%2,%3},{%4,%5,%6,%7},{%8,%9},{%0,%1,%2,%3};"
        : "+f"(d[0]), "+f"(d[1]), "+f"(d[2]), "+f"(d[3])
        : "r"(a[0]), "r"(a[1]), "r"(a[2]), "r"(a[3]), "r"(b[0]), "r"(b[1]));
}

// ---------------- fp16 pre-convert (weights) ----------------
__global__ __launch_bounds__(256) void cvt_f16_kernel(const float* __restrict__ src,
                                                      __half* __restrict__ dst, int n4) {
    int i = blockIdx.x * 256 + threadIdx.x;
    if (i >= n4) return;
    float4 v = reinterpret_cast<const float4*>(src)[i];
    __half2 lo = __floats2half2_rn(v.x, v.y);
    __half2 hi = __floats2half2_rn(v.z, v.w);
    reinterpret_cast<__half2*>(dst)[2*i]   = lo;
    reinterpret_cast<__half2*>(dst)[2*i+1] = hi;
}

// ---------------- LayerNorm (writes fp16) ----------------
__global__ __launch_bounds__(256) void ln_kernel(const float* __restrict__ x,
                                                 const float* __restrict__ gamma,
                                                 const float* __restrict__ beta) {
    int row = blockIdx.x;
    int tid = threadIdx.x;
    const float4* xr = reinterpret_cast<const float4*>(x) + (size_t)row * (DIM/4);
    float4 t = xr[tid];
    float s  = t.x + t.y + t.z + t.w;
    float ss = t.x*t.x + t.y*t.y + t.z*t.z + t.w*t.w;
    #pragma unroll
    for (int o = 16; o > 0; o >>= 1) {
        s  += __shfl_xor_sync(0xffffffffu, s,  o);
        ss += __shfl_xor_sync(0xffffffffu, ss, o);
    }
    __shared__ float ws[8], wss[8];
    int w = tid >> 5, l = tid & 31;
    if (l == 0) { ws[w] = s; wss[w] = ss; }
    __syncthreads();
    if (w == 0) {
        float a = (l < 8) ? ws[l]  : 0.f;
        float b = (l < 8) ? wss[l] : 0.f;
        #pragma unroll
        for (int o = 4; o > 0; o >>= 1) {
            a += __shfl_xor_sync(0xffffffffu, a, o);
            b += __shfl_xor_sync(0xffffffffu, b, o);
        }
        if (l == 0) { ws[0] = a; wss[0] = b; }
    }
    __syncthreads();
    float mu  = ws[0]  * (1.f / DIM);
    float var = wss[0] * (1.f / DIM) - mu * mu;
    float r   = rsqrtf(var + 1e-5f);
    float4 gm = reinterpret_cast<const float4*>(gamma)[tid];
    float4 bt = reinterpret_cast<const float4*>(beta)[tid];
    __half2 lo = __floats2half2_rn((t.x - mu) * r * gm.x + bt.x,
                                   (t.y - mu) * r * gm.y + bt.y);
    __half2 hi = __floats2half2_rn((t.z - mu) * r * gm.z + bt.z,
                                   (t.w - mu) * r * gm.w + bt.w);
    reinterpret_cast<__half2*>(g_h)[(size_t)row * (DIM/2) + 2*tid]   = lo;
    reinterpret_cast<__half2*>(g_h)[(size_t)row * (DIM/2) + 2*tid+1] = hi;
}

// ---------------- FP16 GEMM-NT (R3 skeleton, half2 units, m16n8k16) ----------------
// C[m][n] = sum_k A[m][k]*B[n][k]; A,B fp16, C fp32. BM=BN=128, BK=32 halfs, 256 thr.
__global__ __launch_bounds__(256) void gemm_nt_f16(const __half* __restrict__ A,
                                                   const __half* __restrict__ B,
                                                   float* __restrict__ C,
                                                   int M, int N, int K,
                                                   long strideB, long strideC) {
    __shared__ __align__(16) uint32_t As[128 * 20];   // [m][k2], 16 half2 + pad 4
    __shared__ __align__(16) uint32_t Bs[128 * 20];   // [n][k2]
    const __half* Bz = B + (size_t)blockIdx.z * strideB;
    float*        Cz = C + (size_t)blockIdx.z * strideC;
    int m0 = blockIdx.y * 128, n0 = blockIdx.x * 128;
    int tid = threadIdx.x, lane = tid & 31, wid = tid >> 5;
    int wm = (wid & 1) * 64, wn = (wid >> 1) * 32;
    int g = lane >> 2, t = lane & 3;
    float acc[4][4][4] = {};

    for (int k0 = 0; k0 < K; k0 += 32) {
        #pragma unroll
        for (int i = 0; i < 2; i++) {
            int f = tid + 256 * i;          // 0..511
            int r = f >> 2, c4 = f & 3;     // chunk = 8 halfs = 16B
            float4 a = *reinterpret_cast<const float4*>(A  + (size_t)(m0 + r) * K + k0 + c4 * 8);
            *reinterpret_cast<float4*>(&As[r * 20 + c4 * 4]) = a;
            float4 b = *reinterpret_cast<const float4*>(Bz + (size_t)(n0 + r) * K + k0 + c4 * 8);
            *reinterpret_cast<float4*>(&Bs[r * 20 + c4 * 4]) = b;
        }
        __syncthreads();
        #pragma unroll
        for (int ks = 0; ks < 16; ks += 8) {     // two k16 mma steps
            uint32_t aR[4][4], bR[4][2];
            #pragma unroll
            for (int mf = 0; mf < 4; mf++) {
                int mb = wm + mf * 16;
                aR[mf][0] = As[(mb + g    ) * 20 + ks + t    ];
                aR[mf][1] = As[(mb + g + 8) * 20 + ks + t    ];
                aR[mf][2] = As[(mb + g    ) * 20 + ks + t + 4];
                aR[mf][3] = As[(mb + g + 8) * 20 + ks + t + 4];
            }
            #pragma unroll
            for (int nf = 0; nf < 4; nf++) {
                int nb = wn + nf * 8;
                bR[nf][0] = Bs[(nb + g) * 20 + ks + t    ];
                bR[nf][1] = Bs[(nb + g) * 20 + ks + t + 4];
            }
            #pragma unroll
            for (int mf = 0; mf < 4; mf++)
                #pragma unroll
                for (int nf = 0; nf < 4; nf++)
                    mma_f16(acc[mf][nf], aR[mf], bR[nf]);
        }
        __syncthreads();
    }

    #pragma unroll
    for (int mf = 0; mf < 4; mf++)
        #pragma unroll
        for (int nf = 0; nf < 4; nf++) {
            int m = m0 + wm + mf * 16 + g;
            int n = n0 + wn + nf * 8 + 2 * t;
            *reinterpret_cast<float2*>(Cz + (size_t)m * N + n) =
                make_float2(acc[mf][nf][0], acc[mf][nf][1]);
            *reinterpret_cast<float2*>(Cz + (size_t)(m + 8) * N + n) =
                make_float2(acc[mf][nf][2], acc[mf][nf][3]);
        }
}

// ---------------- depthwise causal conv (writes tf32-rounded fp32) ----------------
__global__ __launch_bounds__(256) void conv_kernel(
    const float* __restrict__ const* wptr) {
    int p = blockIdx.y;
    int idx = blockIdx.x * 256 + threadIdx.x;
    int n = idx & (SEQ - 1);
    int c = (idx >> 11) & (INNER - 1);
    int b = idx >> 21;
    const float* row = g_qkv + ((size_t)b * 3 * INNER + (size_t)p * INNER + c) * SEQ;
    int g = c >> 8, cg = c & 255;
    float acc;
    if (g == 0) {
        acc = row[n];
    } else {
        int ksz = 2 * g + 1;
        const float* w  = wptr[p * 6 + (g - 1) * 2] + cg * ksz;
        const float* bb = wptr[p * 6 + (g - 1) * 2 + 1];
        acc = bb[cg];
        for (int t = 0; t < ksz; t++) {
            int m = n - (ksz - 1) + t;
            if (m >= 0) acc += w[t] * row[m];
        }
    }
    float scale = (p == 0) ? 0.125f : 1.0f;
    float* dst = (p == 0 ? g_q : (p == 1 ? g_k : g_v));
    dst[((size_t)b * INNER + c) * SEQ + n] = to_tf32(acc * scale);
}

__device__ const float* g_convw[18];
__global__ void set_convw(const float* a0, const float* a1, const float* a2, const float* a3,
                          const float* a4, const float* a5, const float* a6, const float* a7,
                          const float* a8, const float* a9, const float* a10, const float* a11,
                          const float* a12, const float* a13, const float* a14, const float* a15,
                          const float* a16, const float* a17) {
    g_convw[0]=a0; g_convw[1]=a1; g_convw[2]=a2; g_convw[3]=a3; g_convw[4]=a4; g_convw[5]=a5;
    g_convw[6]=a6; g_convw[7]=a7; g_convw[8]=a8; g_convw[9]=a9; g_convw[10]=a10; g_convw[11]=a11;
    g_convw[12]=a12; g_convw[13]=a13; g_convw[14]=a14; g_convw[15]=a15; g_convw[16]=a16; g_convw[17]=a17;
}

// ---------------- tensor-core flash attention (TF32, R3 structure) ----------------
#define SSTR 72
__global__ __launch_bounds__(128) void attn_tc(const float* __restrict__ slopes) {
    extern __shared__ float sm[];
    float* Ks  = sm;                 // [d][j] 64 x 72
    float* Vs  = Ks + 64*SSTR;       // [d][j]
    float* QPs = Vs + 64*SSTR;       // Q: [d][i], later P: [i][j]

    int it = blockIdx.x, i0 = it * 64;
    int bh = blockIdx.y, b = bh >> 4, h = bh & 15;
    float slope = slopes[h];
    int tid = threadIdx.x, lane = tid & 31, w = tid >> 5;
    int g = lane >> 2, t = lane & 3;
    int mb = w * 16;
    const float* Qb = g_q + (size_t)bh * DH * SEQ;
    const float* Kb = g_k + (size_t)bh * DH * SEQ;
    const float* Vb = g_v + (size_t)bh * DH * SEQ;

    #pragma unroll
    for (int ii = 0; ii < 8; ii++) {
        int f = tid + 128 * ii, d = f >> 4, c4 = f & 15;
        float4 v = *reinterpret_cast<const float4*>(Qb + (size_t)d * SEQ + i0 + c4 * 4);
        *reinterpret_cast<float4*>(&QPs[d * SSTR + c4 * 4]) = v;
    }
    __syncthreads();

    uint32_t aQ[8][4];
    #pragma unroll
    for (int ks = 0; ks < 8; ks++) {
        aQ[ks][0] = *reinterpret_cast<uint32_t*>(&QPs[(ks*8 + t    ) * SSTR + mb + g    ]);
        aQ[ks][1] = *reinterpret_cast<uint32_t*>(&QPs[(ks*8 + t    ) * SSTR + mb + g + 8]);
        aQ[ks][2] = *reinterpret_cast<uint32_t*>(&QPs[(ks*8 + t + 4) * SSTR + mb + g    ]);
        aQ[ks][3] = *reinterpret_cast<uint32_t*>(&QPs[(ks*8 + t + 4) * SSTR + mb + g + 8]);
    }

    float o[8][4] = {};
    float m0 = -1e30f, m1 = -1e30f, l0 = 0.f, l1 = 0.f;

    for (int jt = 0; jt <= it; jt++) {
        int j0 = jt * 64;
        __syncthreads();
        #pragma unroll
        for (int ii = 0; ii < 8; ii++) {
            int f = tid + 128 * ii, d = f >> 4, c4 = f & 15;
            float4 kv = *reinterpret_cast<const float4*>(Kb + (size_t)d * SEQ + j0 + c4 * 4);
            *reinterpret_cast<float4*>(&Ks[d * SSTR + c4 * 4]) = kv;
            float4 vv = *reinterpret_cast<const float4*>(Vb + (size_t)d * SEQ + j0 + c4 * 4);
            *reinterpret_cast<float4*>(&Vs[d * SSTR + c4 * 4]) = vv;
        }
        __syncthreads();

        float sF[8][4] = {};
        #pragma unroll
        for (int ks = 0; ks < 8; ks++) {
            #pragma unroll
            for (int nf = 0; nf < 8; nf++) {
                uint32_t bR[2];
                bR[0] = *reinterpret_cast<uint32_t*>(&Ks[(ks*8 + t    ) * SSTR + nf*8 + g]);
                bR[1] = *reinterpret_cast<uint32_t*>(&Ks[(ks*8 + t + 4) * SSTR + nf*8 + g]);
                mma_tf32(sF[nf], aQ[ks], bR);
            }
        }

        int ir0 = i0 + mb + g, ir1 = ir0 + 8;
        float mloc0 = -1e30f, mloc1 = -1e30f;
        #pragma unroll
        for (int nf = 0; nf < 8; nf++) {
            int jc = j0 + nf*8 + 2*t;
            float v0 = sF[nf][0] + slope * (float)(jc     - ir0);
            float v1 = sF[nf][1] + slope * (float)(jc + 1 - ir0);
            float v2 = sF[nf][2] + slope * (float)(jc     - ir1);
            float v3 = sF[nf][3] + slope * (float)(jc + 1 - ir1);
            if (jc     > ir0) v0 = -1e30f;
            if (jc + 1 > ir0) v1 = -1e30f;
            if (jc     > ir1) v2 = -1e30f;
            if (jc + 1 > ir1) v3 = -1e30f;
            sF[nf][0] = v0; sF[nf][1] = v1; sF[nf][2] = v2; sF[nf][3] = v3;
            mloc0 = fmaxf(mloc0, fmaxf(v0, v1));
            mloc1 = fmaxf(mloc1, fmaxf(v2, v3));
        }
        mloc0 = fmaxf(mloc0, __shfl_xor_sync(0xffffffffu, mloc0, 1));
        mloc0 = fmaxf(mloc0, __shfl_xor_sync(0xffffffffu, mloc0, 2));
        mloc1 = fmaxf(mloc1, __shfl_xor_sync(0xffffffffu, mloc1, 1));
        mloc1 = fmaxf(mloc1, __shfl_xor_sync(0xffffffffu, mloc1, 2));
        float mn0 = fmaxf(m0, mloc0), mn1 = fmaxf(m1, mloc1);
        float sc0 = __expf(m0 - mn0), sc1 = __expf(m1 - mn1);
        float sum0 = 0.f, sum1 = 0.f;
        #pragma unroll
        for (int nf = 0; nf < 8; nf++) {
            sF[nf][0] = __expf(sF[nf][0] - mn0); sum0 += sF[nf][0];
            sF[nf][1] = __expf(sF[nf][1] - mn0); sum0 += sF[nf][1];
            sF[nf][2] = __expf(sF[nf][2] - mn1); sum1 += sF[nf][2];
            sF[nf][3] = __expf(sF[nf][3] - mn1); sum1 += sF[nf][3];
        }
        sum0 += __shfl_xor_sync(0xffffffffu, sum0, 1);
        sum0 += __shfl_xor_sync(0xffffffffu, sum0, 2);
        sum1 += __shfl_xor_sync(0xffffffffu, sum1, 1);
        sum1 += __shfl_xor_sync(0xffffffffu, sum1, 2);
        l0 = l0 * sc0 + sum0; l1 = l1 * sc1 + sum1;
        m0 = mn0; m1 = mn1;
        #pragma unroll
        for (int nf = 0; nf < 8; nf++) {
            o[nf][0] *= sc0; o[nf][1] *= sc0;
            o[nf][2] *= sc1; o[nf][3] *= sc1;
        }

        #pragma unroll
        for (int nf = 0; nf < 8; nf++) {
            *reinterpret_cast<float2*>(&QPs[(mb + g    ) * SSTR + nf*8 + 2*t]) =
                make_float2(to_tf32(sF[nf][0]), to_tf32(sF[nf][1]));
            *reinterpret_cast<float2*>(&QPs[(mb + g + 8) * SSTR + nf*8 + 2*t]) =
                make_float2(to_tf32(sF[nf][2]), to_tf32(sF[nf][3]));
        }
        __syncwarp();

        #pragma unroll
        for (int ks = 0; ks < 8; ks++) {
            uint32_t aP[4];
            aP[0] = *reinterpret_cast<uint32_t*>(&QPs[(mb + g    ) * SSTR + ks*8 + t    ]);
            aP[1] = *reinterpret_cast<uint32_t*>(&QPs[(mb + g + 8) * SSTR + ks*8 + t    ]);
            aP[2] = *reinterpret_cast<uint32_t*>(&QPs[(mb + g    ) * SSTR + ks*8 + t + 4]);
            aP[3] = *reinterpret_cast<uint32_t*>(&QPs[(mb + g + 8) * SSTR + ks*8 + t + 4]);
            #pragma unroll
            for (int nf = 0; nf < 8; nf++) {
                uint32_t bR[2];
                bR[0] = *reinterpret_cast<uint32_t*>(&Vs[(nf*8 + g) * SSTR + ks*8 + t    ]);
                bR[1] = *reinterpret_cast<uint32_t*>(&Vs[(nf*8 + g) * SSTR + ks*8 + t + 4]);
                mma_tf32(o[nf], aP, bR);
            }
        }
    }

    // normalize + write (B,N,INNER) as fp16 for the out-proj
    float inv0 = 1.f / l0, inv1 = 1.f / l1;
    int r0 = i0 + mb + g;
    #pragma unroll
    for (int nf = 0; nf < 8; nf++) {
        int col = h * DH + nf*8 + 2*t;
        *reinterpret_cast<__half2*>(&g_ao[((size_t)b * SEQ + r0    ) * INNER + col]) =
            __floats2half2_rn(o[nf][0] * inv0, o[nf][1] * inv0);
        *reinterpret_cast<__half2*>(&g_ao[((size_t)b * SEQ + r0 + 8) * INNER + col]) =
            __floats2half2_rn(o[nf][2] * inv1, o[nf][3] * inv1);
    }
}

// ---------------- launch ----------------
extern "C" void kernel_launch(void* const* d_in, const int* in_sizes, int n_in,
                              void* d_out, int out_size) {
    const float* x      = (const float*)d_in[0];
    const float* gamma  = (const float*)d_in[1];
    const float* beta   = (const float*)d_in[2];
    const float* w_qkv  = (const float*)d_in[3];
    const float* slopes = (const float*)d_in[22];
    const float* w_out  = (const float*)d_in[23];

    __half *ph, *pao, *pwqkv, *pwout;
    float *pqkv;
    cudaGetSymbolAddress((void**)&ph,    g_h);
    cudaGetSymbolAddress((void**)&pqkv,  g_qkv);
    cudaGetSymbolAddress((void**)&pao,   g_ao);
    cudaGetSymbolAddress((void**)&pwqkv, g_wqkv);
    cudaGetSymbolAddress((void**)&pwout, g_wout);
    const float** pconvw;
    cudaGetSymbolAddress((void**)&pconvw, g_convw);

    // 0) conv weight ptrs + fp16 weight conversion
    set_convw<<<1, 1>>>(
        (const float*)d_in[4],  (const float*)d_in[5],  (const float*)d_in[6],
        (const float*)d_in[7],  (const float*)d_in[8],  (const float*)d_in[9],
        (const float*)d_in[10], (const float*)d_in[11], (const float*)d_in[12],
        (const float*)d_in[13], (const float*)d_in[14], (const float*)d_in[15],
        (const float*)d_in[16], (const float*)d_in[17], (const float*)d_in[18],
        (const float*)d_in[19], (const float*)d_in[20], (const float*)d_in[21]);
    cvt_f16_kernel<<<(3*INNER*DIM/4 + 255)/256, 256>>>(w_qkv, pwqkv, 3*INNER*DIM/4);
    cvt_f16_kernel<<<(DIM*INNER/4   + 255)/256, 256>>>(w_out, pwout, DIM*INNER/4);

    // 1) LayerNorm (fp16 out)
    ln_kernel<<<BATCH * SEQ, 256>>>(x, gamma, beta);

    // 2) QKV GEMM (fp16 in, fp32 out)
    gemm_nt_f16<<<dim3(SEQ/128, 3*INNER/128, BATCH), 256>>>(
        pwqkv, ph, pqkv, 3*INNER, SEQ, DIM,
        (long)SEQ * DIM, (long)3 * INNER * SEQ);

    // 3) depthwise causal convs (tf32-rounded fp32 out, q scaled)
    int convBlocks = (BATCH * INNER * SEQ) / 256;
    conv_kernel<<<dim3(convBlocks, 3), 256>>>((const float* const*)pconvw);

    // 4) tensor-core flash attention (TF32, R3 structure)
    size_t smem = (size_t)(3 * 64 * SSTR) * sizeof(float);  // 55296 B
    cudaFuncSetAttribute(attn_tc, cudaFuncAttributeMaxDynamicSharedMemorySize, (int)smem);
    attn_tc<<<dim3(SEQ/64, BATCH*HEADS), 128, smem>>>(slopes);

    // 5) output projection (fp16 in, fp32 out)
    gemm_nt_f16<<<dim3(DIM/128, (BATCH*SEQ)/128, 1), 256>>>(
        pao, pwout, (float*)d_out, BATCH*SEQ, DIM, INNER, 0, 0);
}

// round 9
// speedup vs baseline: 1.8832x; 1.2384x over previous
#include <cuda_runtime.h>
#include <cuda_fp16.h>
#include <math.h>
#include <stdint.h>

#define BATCH 2
#define SEQ   2048
#define DIM   1024
#define HEADS 16
#define DH    64
#define INNER 1024

// ---------------- scratch (device globals; no allocs) ----------------
__device__ __half g_h  [BATCH*SEQ*DIM];           // LN output (fp16)
__device__ float  g_qkv[BATCH*3*INNER*SEQ];       // (B, 3*INNER, SEQ) fp32
__device__ __half g_q16[BATCH*HEADS*SEQ*DH];      // [b][h][n][dh], scaled
__device__ __half g_k16[BATCH*HEADS*SEQ*DH];      // [b][h][n][dh]
__device__ __half g_v16[BATCH*HEADS*DH*SEQ];      // [b][h][dh][n]
__device__ __half g_ao [BATCH*SEQ*INNER];         // attention out (fp16)
__device__ __half g_wqkv[3*INNER*DIM];            // fp16 weights
__device__ __half g_wout[DIM*INNER];

// ---------------- helpers ----------------
__device__ __forceinline__ void mma_f16(float* d, const uint32_t* a, const uint32_t* b) {
    asm volatile(
        "mma.sync.aligned.m16n8k16.row.col.f32.f16.f16.f32 "
        "{%0,%1,%2,%3},{%4,%5,%6,%7},{%8,%9},{%0,%1,%2,%3};"
        : "+f"(d[0]), "+f"(d[1]), "+f"(d[2]), "+f"(d[3])
        : "r"(a[0]), "r"(a[1]), "r"(a[2]), "r"(a[3]), "r"(b[0]), "r"(b[1]));
}
__device__ __forceinline__ uint32_t pack_h2(float a, float b) {
    __half2 p = __floats2half2_rn(a, b);
    return *reinterpret_cast<uint32_t*>(&p);
}

// ---------------- fp16 pre-convert (weights) ----------------
__global__ __launch_bounds__(256) void cvt_f16_kernel(const float* __restrict__ src,
                                                      __half* __restrict__ dst, int n4) {
    int i = blockIdx.x * 256 + threadIdx.x;
    if (i >= n4) return;
    float4 v = reinterpret_cast<const float4*>(src)[i];
    reinterpret_cast<__half2*>(dst)[2*i]   = __floats2half2_rn(v.x, v.y);
    reinterpret_cast<__half2*>(dst)[2*i+1] = __floats2half2_rn(v.z, v.w);
}

// ---------------- LayerNorm (writes fp16) ----------------
__global__ __launch_bounds__(256) void ln_kernel(const float* __restrict__ x,
                                                 const float* __restrict__ gamma,
                                                 const float* __restrict__ beta) {
    int row = blockIdx.x;
    int tid = threadIdx.x;
    const float4* xr = reinterpret_cast<const float4*>(x) + (size_t)row * (DIM/4);
    float4 t = xr[tid];
    float s  = t.x + t.y + t.z + t.w;
    float ss = t.x*t.x + t.y*t.y + t.z*t.z + t.w*t.w;
    #pragma unroll
    for (int o = 16; o > 0; o >>= 1) {
        s  += __shfl_xor_sync(0xffffffffu, s,  o);
        ss += __shfl_xor_sync(0xffffffffu, ss, o);
    }
    __shared__ float ws[8], wss[8];
    int w = tid >> 5, l = tid & 31;
    if (l == 0) { ws[w] = s; wss[w] = ss; }
    __syncthreads();
    if (w == 0) {
        float a = (l < 8) ? ws[l]  : 0.f;
        float b = (l < 8) ? wss[l] : 0.f;
        #pragma unroll
        for (int o = 4; o > 0; o >>= 1) {
            a += __shfl_xor_sync(0xffffffffu, a, o);
            b += __shfl_xor_sync(0xffffffffu, b, o);
        }
        if (l == 0) { ws[0] = a; wss[0] = b; }
    }
    __syncthreads();
    float mu  = ws[0]  * (1.f / DIM);
    float var = wss[0] * (1.f / DIM) - mu * mu;
    float r   = rsqrtf(var + 1e-5f);
    float4 gm = reinterpret_cast<const float4*>(gamma)[tid];
    float4 bt = reinterpret_cast<const float4*>(beta)[tid];
    reinterpret_cast<__half2*>(g_h)[(size_t)row * (DIM/2) + 2*tid] =
        __floats2half2_rn((t.x - mu) * r * gm.x + bt.x, (t.y - mu) * r * gm.y + bt.y);
    reinterpret_cast<__half2*>(g_h)[(size_t)row * (DIM/2) + 2*tid+1] =
        __floats2half2_rn((t.z - mu) * r * gm.z + bt.z, (t.w - mu) * r * gm.w + bt.w);
}

// ---------------- FP16 GEMM-NT (unchanged from R8) ----------------
__global__ __launch_bounds__(256) void gemm_nt_f16(const __half* __restrict__ A,
                                                   const __half* __restrict__ B,
                                                   float* __restrict__ C,
                                                   int M, int N, int K,
                                                   long strideB, long strideC) {
    __shared__ __align__(16) uint32_t As[128 * 20];
    __shared__ __align__(16) uint32_t Bs[128 * 20];
    const __half* Bz = B + (size_t)blockIdx.z * strideB;
    float*        Cz = C + (size_t)blockIdx.z * strideC;
    int m0 = blockIdx.y * 128, n0 = blockIdx.x * 128;
    int tid = threadIdx.x, lane = tid & 31, wid = tid >> 5;
    int wm = (wid & 1) * 64, wn = (wid >> 1) * 32;
    int g = lane >> 2, t = lane & 3;
    float acc[4][4][4] = {};

    for (int k0 = 0; k0 < K; k0 += 32) {
        #pragma unroll
        for (int i = 0; i < 2; i++) {
            int f = tid + 256 * i;
            int r = f >> 2, c4 = f & 3;
            float4 a = *reinterpret_cast<const float4*>(A  + (size_t)(m0 + r) * K + k0 + c4 * 8);
            *reinterpret_cast<float4*>(&As[r * 20 + c4 * 4]) = a;
            float4 b = *reinterpret_cast<const float4*>(Bz + (size_t)(n0 + r) * K + k0 + c4 * 8);
            *reinterpret_cast<float4*>(&Bs[r * 20 + c4 * 4]) = b;
        }
        __syncthreads();
        #pragma unroll
        for (int ks = 0; ks < 16; ks += 8) {
            uint32_t aR[4][4], bR[4][2];
            #pragma unroll
            for (int mf = 0; mf < 4; mf++) {
                int mb = wm + mf * 16;
                aR[mf][0] = As[(mb + g    ) * 20 + ks + t    ];
                aR[mf][1] = As[(mb + g + 8) * 20 + ks + t    ];
                aR[mf][2] = As[(mb + g    ) * 20 + ks + t + 4];
                aR[mf][3] = As[(mb + g + 8) * 20 + ks + t + 4];
            }
            #pragma unroll
            for (int nf = 0; nf < 4; nf++) {
                int nb = wn + nf * 8;
                bR[nf][0] = Bs[(nb + g) * 20 + ks + t    ];
                bR[nf][1] = Bs[(nb + g) * 20 + ks + t + 4];
            }
            #pragma unroll
            for (int mf = 0; mf < 4; mf++)
                #pragma unroll
                for (int nf = 0; nf < 4; nf++)
                    mma_f16(acc[mf][nf], aR[mf], bR[nf]);
        }
        __syncthreads();
    }

    #pragma unroll
    for (int mf = 0; mf < 4; mf++)
        #pragma unroll
        for (int nf = 0; nf < 4; nf++) {
            int m = m0 + wm + mf * 16 + g;
            int n = n0 + wn + nf * 8 + 2 * t;
            *reinterpret_cast<float2*>(Cz + (size_t)m * N + n) =
                make_float2(acc[mf][nf][0], acc[mf][nf][1]);
            *reinterpret_cast<float2*>(Cz + (size_t)(m + 8) * N + n) =
                make_float2(acc[mf][nf][2], acc[mf][nf][3]);
        }
}

// ---------------- tiled depthwise causal conv (fp16 out, mma layouts) ----------------
// block = (b, p, head h, 64-position tile). q,k -> [b][h][n][dh]; v -> [b][h][dh][n].
__device__ const float* g_convw[18];
__global__ __launch_bounds__(256) void conv_kernel() {
    __shared__ float  s_in [64 * 72];     // [dh][col], col = n0-8 .. n0+63
    __shared__ __half s_out[64 * 72];     // p<2: [n][dh]; p==2: [dh][n] (stride 72)
    int n0 = blockIdx.x * 64;
    int ct = blockIdx.y;                  // 0..47
    int p  = ct >> 4, h = ct & 15;
    int b  = blockIdx.z;
    int g  = h >> 2;                      // kernel group 0..3
    int tid = threadIdx.x;

    const float* src = g_qkv + ((size_t)(b * 3 + p) * INNER + h * 64) * SEQ;
    for (int idx = tid; idx < 64 * 72; idx += 256) {
        int dh = idx / 72, col = idx % 72;
        int m = n0 - 8 + col;
        s_in[idx] = (m >= 0) ? src[(size_t)dh * SEQ + m] : 0.f;
    }
    __syncthreads();

    int dh = tid >> 2, nb = (tid & 3) * 16;
    float scale = (p == 0) ? 0.125f : 1.0f;
    if (g == 0) {
        for (int s = 0; s < 16; s++) {
            int rel = nb + s;
            float acc = s_in[dh * 72 + 8 + rel] * scale;
            if (p < 2) s_out[rel * 72 + dh] = __float2half(acc);
            else       s_out[dh * 72 + rel] = __float2half(acc);
        }
    } else {
        int ksz = 2 * g + 1;
        int cg  = (h & 3) * 64 + dh;
        const float* w  = g_convw[p * 6 + (g - 1) * 2] + cg * ksz;
        float bias      = g_convw[p * 6 + (g - 1) * 2 + 1][cg];
        float wr[7];
        for (int tt = 0; tt < ksz; tt++) wr[tt] = w[tt];
        for (int s = 0; s < 16; s++) {
            int rel = nb + s;
            float acc = bias;
            int cbase = dh * 72 + 8 + rel - (ksz - 1);
            for (int tt = 0; tt < ksz; tt++) acc += wr[tt] * s_in[cbase + tt];
            acc *= scale;
            if (p < 2) s_out[rel * 72 + dh] = __float2half(acc);
            else       s_out[dh * 72 + rel] = __float2half(acc);
        }
    }
    __syncthreads();

    int row = tid >> 2, chunk = tid & 3;
    const uint4* sp = reinterpret_cast<const uint4*>(&s_out[row * 72 + chunk * 16]);
    __half* dst;
    if (p < 2) {
        __half* base = (p == 0) ? g_q16 : g_k16;
        dst = base + ((size_t)(b * HEADS + h) * SEQ + n0 + row) * DH + chunk * 16;
    } else {
        dst = g_v16 + ((size_t)(b * HEADS + h) * DH + row) * SEQ + n0 + chunk * 16;
    }
    reinterpret_cast<uint4*>(dst)[0] = sp[0];
    reinterpret_cast<uint4*>(dst)[1] = sp[1];
}

__global__ void set_convw(const float* a0, const float* a1, const float* a2, const float* a3,
                          const float* a4, const float* a5, const float* a6, const float* a7,
                          const float* a8, const float* a9, const float* a10, const float* a11,
                          const float* a12, const float* a13, const float* a14, const float* a15,
                          const float* a16, const float* a17) {
    g_convw[0]=a0; g_convw[1]=a1; g_convw[2]=a2; g_convw[3]=a3; g_convw[4]=a4; g_convw[5]=a5;
    g_convw[6]=a6; g_convw[7]=a7; g_convw[8]=a8; g_convw[9]=a9; g_convw[10]=a10; g_convw[11]=a11;
    g_convw[12]=a12; g_convw[13]=a13; g_convw[14]=a14; g_convw[15]=a15; g_convw[16]=a16; g_convw[17]=a17;
}

// ---------------- fp16 tensor-core flash attention ----------------
// Q,K [bh][n][dh]; V [bh][dh][n]. 64 rows/block, 64-col tiles, 4 warps.
// P stays in registers (softmax frag layout == fp16 A-frag layout).
#define AST 72
__global__ __launch_bounds__(128) void attn_f16(const float* __restrict__ slopes) {
    __shared__ __align__(16) __half Ksh[64 * AST];   // [j][d]
    __shared__ __align__(16) __half Vsh[64 * AST];   // [d][j]

    int it = blockIdx.x, i0 = it * 64;
    int bh = blockIdx.y, b = bh >> 4, h = bh & 15;
    float slope = slopes[h];
    int tid = threadIdx.x, lane = tid & 31, w = tid >> 5;
    int g = lane >> 2, t = lane & 3;
    int mb = w * 16;
    const __half* Qg = g_q16 + (size_t)bh * SEQ * DH;
    const __half* Kg = g_k16 + (size_t)bh * SEQ * DH;
    const __half* Vg = g_v16 + (size_t)bh * DH * SEQ;

    // Q fragments straight from gmem
    uint32_t aQ[4][4];
    int iq0 = i0 + mb + g, iq1 = iq0 + 8;
    #pragma unroll
    for (int ks = 0; ks < 4; ks++) {
        int base = ks * 16 + 2 * t;
        aQ[ks][0] = *reinterpret_cast<const uint32_t*>(&Qg[(size_t)iq0 * DH + base]);
        aQ[ks][1] = *reinterpret_cast<const uint32_t*>(&Qg[(size_t)iq1 * DH + base]);
        aQ[ks][2] = *reinterpret_cast<const uint32_t*>(&Qg[(size_t)iq0 * DH + base + 8]);
        aQ[ks][3] = *reinterpret_cast<const uint32_t*>(&Qg[(size_t)iq1 * DH + base + 8]);
    }

    float o[8][4] = {};
    float m0 = -1e30f, m1 = -1e30f, l0 = 0.f, l1 = 0.f;

    for (int jt = 0; jt <= it; jt++) {
        int j0 = jt * 64;
        __syncthreads();
        {   // load K [j][d] and V [d][j] tiles, plain coalesced copies
            int r = tid >> 1, c = (tid & 1) * 32;
            const uint4* ks_ = reinterpret_cast<const uint4*>(&Kg[(size_t)(j0 + r) * DH + c]);
            uint4* kd = reinterpret_cast<uint4*>(&Ksh[r * AST + c]);
            kd[0] = ks_[0]; kd[1] = ks_[1]; kd[2] = ks_[2]; kd[3] = ks_[3];
            const uint4* vs_ = reinterpret_cast<const uint4*>(&Vg[(size_t)r * SEQ + j0 + c]);
            uint4* vd = reinterpret_cast<uint4*>(&Vsh[r * AST + c]);
            vd[0] = vs_[0]; vd[1] = vs_[1]; vd[2] = vs_[2]; vd[3] = vs_[3];
        }
        __syncthreads();

        // S = Q K^T  (4 k16 steps over d, 8 n-frags over j)
        float sF[8][4] = {};
        #pragma unroll
        for (int ks = 0; ks < 4; ks++) {
            #pragma unroll
            for (int nf = 0; nf < 8; nf++) {
                uint32_t bR[2];
                const __half* kp = &Ksh[(nf*8 + g) * AST + ks * 16 + 2 * t];
                bR[0] = *reinterpret_cast<const uint32_t*>(kp);
                bR[1] = *reinterpret_cast<const uint32_t*>(kp + 8);
                mma_f16(sF[nf], aQ[ks], bR);
            }
        }

        // bias + causal mask + online softmax
        int ir0 = i0 + mb + g, ir1 = ir0 + 8;
        float mloc0 = -1e30f, mloc1 = -1e30f;
        #pragma unroll
        for (int nf = 0; nf < 8; nf++) {
            int jc = j0 + nf*8 + 2*t;
            float v0 = sF[nf][0] + slope * (float)(jc     - ir0);
            float v1 = sF[nf][1] + slope * (float)(jc + 1 - ir0);
            float v2 = sF[nf][2] + slope * (float)(jc     - ir1);
            float v3 = sF[nf][3] + slope * (float)(jc + 1 - ir1);
            if (jc     > ir0) v0 = -1e30f;
            if (jc + 1 > ir0) v1 = -1e30f;
            if (jc     > ir1) v2 = -1e30f;
            if (jc + 1 > ir1) v3 = -1e30f;
            sF[nf][0] = v0; sF[nf][1] = v1; sF[nf][2] = v2; sF[nf][3] = v3;
            mloc0 = fmaxf(mloc0, fmaxf(v0, v1));
            mloc1 = fmaxf(mloc1, fmaxf(v2, v3));
        }
        mloc0 = fmaxf(mloc0, __shfl_xor_sync(0xffffffffu, mloc0, 1));
        mloc0 = fmaxf(mloc0, __shfl_xor_sync(0xffffffffu, mloc0, 2));
        mloc1 = fmaxf(mloc1, __shfl_xor_sync(0xffffffffu, mloc1, 1));
        mloc1 = fmaxf(mloc1, __shfl_xor_sync(0xffffffffu, mloc1, 2));
        float mn0 = fmaxf(m0, mloc0), mn1 = fmaxf(m1, mloc1);
        float sc0 = __expf(m0 - mn0), sc1 = __expf(m1 - mn1);
        float sum0 = 0.f, sum1 = 0.f;
        #pragma unroll
        for (int nf = 0; nf < 8; nf++) {
            sF[nf][0] = __expf(sF[nf][0] - mn0); sum0 += sF[nf][0];
            sF[nf][1] = __expf(sF[nf][1] - mn0); sum0 += sF[nf][1];
            sF[nf][2] = __expf(sF[nf][2] - mn1); sum1 += sF[nf][2];
            sF[nf][3] = __expf(sF[nf][3] - mn1); sum1 += sF[nf][3];
        }
        sum0 += __shfl_xor_sync(0xffffffffu, sum0, 1);
        sum0 += __shfl_xor_sync(0xffffffffu, sum0, 2);
        sum1 += __shfl_xor_sync(0xffffffffu, sum1, 1);
        sum1 += __shfl_xor_sync(0xffffffffu, sum1, 2);
        l0 = l0 * sc0 + sum0; l1 = l1 * sc1 + sum1;
        m0 = mn0; m1 = mn1;
        #pragma unroll
        for (int nf = 0; nf < 8; nf++) {
            o[nf][0] *= sc0; o[nf][1] *= sc0;
            o[nf][2] *= sc1; o[nf][3] *= sc1;
        }

        // pack P into fp16 A-fragments (registers only)
        uint32_t aP[4][4];
        #pragma unroll
        for (int ks = 0; ks < 4; ks++) {
            aP[ks][0] = pack_h2(sF[2*ks  ][0], sF[2*ks  ][1]);
            aP[ks][1] = pack_h2(sF[2*ks  ][2], sF[2*ks  ][3]);
            aP[ks][2] = pack_h2(sF[2*ks+1][0], sF[2*ks+1][1]);
            aP[ks][3] = pack_h2(sF[2*ks+1][2], sF[2*ks+1][3]);
        }

        // O += P V  (4 k16 steps over j, 8 n-frags over d)
        #pragma unroll
        for (int ks = 0; ks < 4; ks++) {
            #pragma unroll
            for (int nf = 0; nf < 8; nf++) {
                uint32_t bR[2];
                const __half* vp = &Vsh[(nf*8 + g) * AST + ks * 16 + 2 * t];
                bR[0] = *reinterpret_cast<const uint32_t*>(vp);
                bR[1] = *reinterpret_cast<const uint32_t*>(vp + 8);
                mma_f16(o[nf], aP[ks], bR);
            }
        }
    }

    // normalize + write (B,N,INNER) as fp16
    float inv0 = 1.f / l0, inv1 = 1.f / l1;
    int r0 = i0 + mb + g;
    #pragma unroll
    for (int nf = 0; nf < 8; nf++) {
        int col = h * DH + nf*8 + 2*t;
        *reinterpret_cast<__half2*>(&g_ao[((size_t)b * SEQ + r0    ) * INNER + col]) =
            __floats2half2_rn(o[nf][0] * inv0, o[nf][1] * inv0);
        *reinterpret_cast<__half2*>(&g_ao[((size_t)b * SEQ + r0 + 8) * INNER + col]) =
            __floats2half2_rn(o[nf][2] * inv1, o[nf][3] * inv1);
    }
}

// ---------------- launch ----------------
extern "C" void kernel_launch(void* const* d_in, const int* in_sizes, int n_in,
                              void* d_out, int out_size) {
    const float* x      = (const float*)d_in[0];
    const float* gamma  = (const float*)d_in[1];
    const float* beta   = (const float*)d_in[2];
    const float* w_qkv  = (const float*)d_in[3];
    const float* slopes = (const float*)d_in[22];
    const float* w_out  = (const float*)d_in[23];

    __half *ph, *pao, *pwqkv, *pwout;
    float *pqkv;
    cudaGetSymbolAddress((void**)&ph,    g_h);
    cudaGetSymbolAddress((void**)&pqkv,  g_qkv);
    cudaGetSymbolAddress((void**)&pao,   g_ao);
    cudaGetSymbolAddress((void**)&pwqkv, g_wqkv);
    cudaGetSymbolAddress((void**)&pwout, g_wout);

    // 0) conv weight ptrs + fp16 weight conversion
    set_convw<<<1, 1>>>(
        (const float*)d_in[4],  (const float*)d_in[5],  (const float*)d_in[6],
        (const float*)d_in[7],  (const float*)d_in[8],  (const float*)d_in[9],
        (const float*)d_in[10], (const float*)d_in[11], (const float*)d_in[12],
        (const float*)d_in[13], (const float*)d_in[14], (const float*)d_in[15],
        (const float*)d_in[16], (const float*)d_in[17], (const float*)d_in[18],
        (const float*)d_in[19], (const float*)d_in[20], (const float*)d_in[21]);
    cvt_f16_kernel<<<(3*INNER*DIM/4 + 255)/256, 256>>>(w_qkv, pwqkv, 3*INNER*DIM/4);
    cvt_f16_kernel<<<(DIM*INNER/4   + 255)/256, 256>>>(w_out, pwout, DIM*INNER/4);

    // 1) LayerNorm (fp16 out)
    ln_kernel<<<BATCH * SEQ, 256>>>(x, gamma, beta);

    // 2) QKV GEMM (fp16 in, fp32 out)
    gemm_nt_f16<<<dim3(SEQ/128, 3*INNER/128, BATCH), 256>>>(
        pwqkv, ph, pqkv, 3*INNER, SEQ, DIM,
        (long)SEQ * DIM, (long)3 * INNER * SEQ);

    // 3) tiled depthwise causal convs -> fp16 q/k [n][dh], v [dh][n]
    conv_kernel<<<dim3(SEQ/64, 48, BATCH), 256>>>();

    // 4) fp16 tensor-core flash attention
    attn_f16<<<dim3(SEQ/64, BATCH*HEADS), 128>>>(slopes);

    // 5) output projection (fp16 in, fp32 out)
    gemm_nt_f16<<<dim3(DIM/128, (BATCH*SEQ)/128, 1), 256>>>(
        pao, pwout, (float*)d_out, BATCH*SEQ, DIM, INNER, 0, 0);
}